// round 4
// baseline (speedup 1.0000x reference)
#include <cuda_runtime.h>
#include <math.h>

#define S_LEN   2048
#define DMODEL  1024
#define NHEADS  16
#define DK      64
#define BATCH   2
#define NTOK    (BATCH * S_LEN)     // 4096
#define BHALL   (BATCH * NHEADS)    // 32

// ---------------- scratch (device globals; no allocation allowed) ----------
__device__ float g_Q[BHALL * DK * S_LEN];     // (bh, d, s)  dk-major
__device__ float g_K[BHALL * DK * S_LEN];     // (bh, d, s)  dk-major
__device__ float g_V[BHALL * S_LEN * DK];     // (bh, s, d)
__device__ float g_O[NTOK * DMODEL];          // token-major attention output
__device__ float g_cs[BHALL * S_LEN];
__device__ float g_sn[BHALL * S_LEN];

// ============================================================================
// SGEMM: C = A(MxK) @ B(KxN) + bias, 128x128 tiles, BK=16, 256 thr, 8x8 micro
// MODE 0: C[m*N + n]                       (token-major)
// MODE 1: C[(bh*S + s)*DK + d]             (head-major, for V)
// MODE 2: C[(bh*DK + d)*S + s]             (dk-major,  for Q/K)
// ============================================================================
#define BM 128
#define BN 128
#define BKK 16
#define LDA (BM + 4)
#define LDB (BN + 4)

template <int MODE>
__global__ void __launch_bounds__(256, 2) sgemm128(
    const float* __restrict__ A, const float* __restrict__ B,
    const float* __restrict__ bias, float* __restrict__ C,
    int M, int N, int K)
{
    __shared__ float At[2][BKK * LDA];
    __shared__ float Bs[2][BKK * LDB];

    const int tid = threadIdx.x;
    const int tx = tid & 15;
    const int ty = tid >> 4;
    const int m0 = blockIdx.y * BM;
    const int n0 = blockIdx.x * BN;

    // A tile: 128 rows x 16 cols = 512 float4 (each thread: 2)
    const int am0 = tid >> 2;            const int ak0 = (tid & 3) << 2;
    const int am1 = (tid + 256) >> 2;    const int ak1 = ((tid + 256) & 3) << 2;
    // B tile: 16 rows x 128 cols = 512 float4
    const int bk0 = tid >> 5;            const int bn0 = (tid & 31) << 2;
    const int bk1 = (tid + 256) >> 5;    const int bn1 = ((tid + 256) & 31) << 2;

    float4 ra0, ra1, rb0, rb1;

    // prologue: tile 0
    ra0 = *(const float4*)&A[(size_t)(m0 + am0) * K + ak0];
    ra1 = *(const float4*)&A[(size_t)(m0 + am1) * K + ak1];
    rb0 = *(const float4*)&B[(size_t)bk0 * N + n0 + bn0];
    rb1 = *(const float4*)&B[(size_t)bk1 * N + n0 + bn1];

    At[0][(ak0 + 0) * LDA + am0] = ra0.x;
    At[0][(ak0 + 1) * LDA + am0] = ra0.y;
    At[0][(ak0 + 2) * LDA + am0] = ra0.z;
    At[0][(ak0 + 3) * LDA + am0] = ra0.w;
    At[0][(ak1 + 0) * LDA + am1] = ra1.x;
    At[0][(ak1 + 1) * LDA + am1] = ra1.y;
    At[0][(ak1 + 2) * LDA + am1] = ra1.z;
    At[0][(ak1 + 3) * LDA + am1] = ra1.w;
    *(float4*)&Bs[0][bk0 * LDB + bn0] = rb0;
    *(float4*)&Bs[0][bk1 * LDB + bn1] = rb1;
    __syncthreads();

    float acc[8][8];
#pragma unroll
    for (int i = 0; i < 8; i++)
#pragma unroll
        for (int j = 0; j < 8; j++) acc[i][j] = 0.f;

    const int KT = K / BKK;
    for (int kt = 0; kt < KT; ++kt) {
        const int buf = kt & 1;
        if (kt + 1 < KT) {
            const int k0 = (kt + 1) * BKK;
            ra0 = *(const float4*)&A[(size_t)(m0 + am0) * K + k0 + ak0];
            ra1 = *(const float4*)&A[(size_t)(m0 + am1) * K + k0 + ak1];
            rb0 = *(const float4*)&B[(size_t)(k0 + bk0) * N + n0 + bn0];
            rb1 = *(const float4*)&B[(size_t)(k0 + bk1) * N + n0 + bn1];
        }
#pragma unroll
        for (int kk = 0; kk < BKK; ++kk) {
            float a[8], bb[8];
            *(float4*)&a[0]  = *(const float4*)&At[buf][kk * LDA + ty * 8];
            *(float4*)&a[4]  = *(const float4*)&At[buf][kk * LDA + ty * 8 + 4];
            *(float4*)&bb[0] = *(const float4*)&Bs[buf][kk * LDB + tx * 8];
            *(float4*)&bb[4] = *(const float4*)&Bs[buf][kk * LDB + tx * 8 + 4];
#pragma unroll
            for (int i = 0; i < 8; i++)
#pragma unroll
                for (int j = 0; j < 8; j++) acc[i][j] += a[i] * bb[j];
        }
        if (kt + 1 < KT) {
            const int nb = 1 - buf;
            At[nb][(ak0 + 0) * LDA + am0] = ra0.x;
            At[nb][(ak0 + 1) * LDA + am0] = ra0.y;
            At[nb][(ak0 + 2) * LDA + am0] = ra0.z;
            At[nb][(ak0 + 3) * LDA + am0] = ra0.w;
            At[nb][(ak1 + 0) * LDA + am1] = ra1.x;
            At[nb][(ak1 + 1) * LDA + am1] = ra1.y;
            At[nb][(ak1 + 2) * LDA + am1] = ra1.z;
            At[nb][(ak1 + 3) * LDA + am1] = ra1.w;
            *(float4*)&Bs[nb][bk0 * LDB + bn0] = rb0;
            *(float4*)&Bs[nb][bk1 * LDB + bn1] = rb1;
            __syncthreads();
        }
    }

    float bv[8];
#pragma unroll
    for (int j = 0; j < 8; j++) bv[j] = bias[n0 + tx * 8 + j];

#pragma unroll
    for (int i = 0; i < 8; i++) {
        const int m = m0 + ty * 8 + i;
        if (MODE == 0) {
            float4 o0, o1;
            o0.x = acc[i][0] + bv[0]; o0.y = acc[i][1] + bv[1];
            o0.z = acc[i][2] + bv[2]; o0.w = acc[i][3] + bv[3];
            o1.x = acc[i][4] + bv[4]; o1.y = acc[i][5] + bv[5];
            o1.z = acc[i][6] + bv[6]; o1.w = acc[i][7] + bv[7];
            *(float4*)&C[(size_t)m * N + n0 + tx * 8]     = o0;
            *(float4*)&C[(size_t)m * N + n0 + tx * 8 + 4] = o1;
        } else {
            const int b = m >> 11;          // m / 2048
            const int s = m & 2047;
#pragma unroll
            for (int j = 0; j < 8; j++) {
                const int n = n0 + tx * 8 + j;
                const int h = n >> 6, d = n & 63;
                const int bh = b * NHEADS + h;
                const float v = acc[i][j] + bv[j];
                if (MODE == 1)
                    C[((size_t)bh * S_LEN + s) * DK + d] = v;
                else
                    C[((size_t)bh * DK + d) * S_LEN + s] = v;
            }
        }
    }
}

// ============================================================================
// Phase kernel: phase = x @ Wp + bp ; cos/sin stored per (bh, s)
// One block (128 thr) per token; 16 heads x 8 partial threads each.
// ============================================================================
__global__ void __launch_bounds__(128) phase_kernel(
    const float* __restrict__ x, const float* __restrict__ Wp,
    const float* __restrict__ bp, float* __restrict__ cs, float* __restrict__ sn)
{
    __shared__ float xs[DMODEL];
    const int m = blockIdx.x;
    for (int i = threadIdx.x; i < DMODEL / 4; i += 128)
        *(float4*)&xs[i * 4] = *(const float4*)&x[(size_t)m * DMODEL + i * 4];
    __syncthreads();

    const int h = threadIdx.x >> 3;
    const int part = threadIdx.x & 7;
    float sum = 0.f;
    const int k0 = part * 128;
#pragma unroll 4
    for (int k = k0; k < k0 + 128; ++k) sum += xs[k] * Wp[k * NHEADS + h];
#pragma unroll
    for (int off = 4; off >= 1; off >>= 1)
        sum += __shfl_xor_sync(0xffffffffu, sum, off);

    if (part == 0) {
        const float ph = sum + bp[h];
        const int b = m >> 11, s = m & 2047;
        const int bh = b * NHEADS + h;
        float sv, cv;
        sincosf(ph, &sv, &cv);
        cs[bh * S_LEN + s] = cv;
        sn[bh * S_LEN + s] = sv;
    }
}

// ============================================================================
// Flash attention, fp32. TQ=128 queries x TK=128 keys per tile, dk=64.
// 256 thr: 16x16 grid; QK micro 8x8, PV micro 8x4. Rank-2 coherence epilogue.
// ============================================================================
#define TQ 128
#define TK 128
#define QT_OFF 0                       // Qt[64][132]
#define KT_OFF (64 * 132)              // Kt[64][132]
#define VS_OFF (KT_OFF + 64 * 132)     // Vs[128][68]
#define PS_OFF (VS_OFF + 128 * 68)     // Ps[128][132]
#define KC_OFF (PS_OFF + 128 * 132)    // kc[128]
#define KS_OFF (KC_OFF + 128)          // ks[128]
#define ATT_SMEM_FLOATS (KS_OFF + 128)
#define ATT_SMEM_BYTES (ATT_SMEM_FLOATS * 4)

__global__ void __launch_bounds__(256, 1) attn_kernel(
    const float* __restrict__ Q, const float* __restrict__ K,
    const float* __restrict__ V, const float* __restrict__ cs,
    const float* __restrict__ sn, const float* __restrict__ alpha,
    float* __restrict__ O)
{
    extern __shared__ float sm[];
    const int tid = threadIdx.x;
    const int tx = tid & 15;
    const int ty = tid >> 4;
    const int bh = blockIdx.y;
    const int q0 = blockIdx.x * TQ;
    const float scale = 0.125f;             // dk^-0.5
    const float alp = alpha[bh & (NHEADS - 1)];

    // Load Qt[k][r] (dk-major global -> coalesced rows)
#pragma unroll
    for (int i = 0; i < 8; i++) {
        const int idx = tid + i * 256;      // 0..2047
        const int k = idx >> 5;
        const int r4 = (idx & 31) << 2;
        *(float4*)&sm[QT_OFF + k * 132 + r4] =
            *(const float4*)&Q[((size_t)bh * DK + k) * S_LEN + q0 + r4];
    }

    float qc[8], qs[8];
#pragma unroll
    for (int i = 0; i < 8; i++) {
        const int r = ty * 8 + i;
        qc[i] = cs[bh * S_LEN + q0 + r];
        qs[i] = sn[bh * S_LEN + q0 + r];
    }

    float m_i[8], l_i[8], o_acc[8][4];
#pragma unroll
    for (int i = 0; i < 8; i++) {
        m_i[i] = -1e30f; l_i[i] = 0.f;
#pragma unroll
        for (int j = 0; j < 4; j++) o_acc[i][j] = 0.f;
    }

    for (int kt = 0; kt < S_LEN / TK; ++kt) {
        const int c0 = kt * TK;
        __syncthreads();   // prev iter's PV done (and Qt visible on kt=0 path below)

        // Load Kt[k][c]
#pragma unroll
        for (int i = 0; i < 8; i++) {
            const int idx = tid + i * 256;
            const int k = idx >> 5;
            const int c4 = (idx & 31) << 2;
            *(float4*)&sm[KT_OFF + k * 132 + c4] =
                *(const float4*)&K[((size_t)bh * DK + k) * S_LEN + c0 + c4];
        }
        // Load Vs[c][d]
#pragma unroll
        for (int i = 0; i < 8; i++) {
            const int idx = tid + i * 256;
            const int c = idx >> 4;
            const int d4 = (idx & 15) << 2;
            *(float4*)&sm[VS_OFF + c * 68 + d4] =
                *(const float4*)&V[((size_t)bh * S_LEN + c0 + c) * DK + d4];
        }
        if (tid < 128) {
            sm[KC_OFF + tid] = cs[bh * S_LEN + c0 + tid];
            sm[KS_OFF + tid] = sn[bh * S_LEN + c0 + tid];
        }
        __syncthreads();

        // ---- QK^T ----
        float acc[8][8];
#pragma unroll
        for (int i = 0; i < 8; i++)
#pragma unroll
            for (int j = 0; j < 8; j++) acc[i][j] = 0.f;

#pragma unroll 8
        for (int k = 0; k < DK; ++k) {
            float a[8], bb[8];
            *(float4*)&a[0]  = *(const float4*)&sm[QT_OFF + k * 132 + ty * 8];
            *(float4*)&a[4]  = *(const float4*)&sm[QT_OFF + k * 132 + ty * 8 + 4];
            *(float4*)&bb[0] = *(const float4*)&sm[KT_OFF + k * 132 + tx * 8];
            *(float4*)&bb[4] = *(const float4*)&sm[KT_OFF + k * 132 + tx * 8 + 4];
#pragma unroll
            for (int i = 0; i < 8; i++)
#pragma unroll
                for (int j = 0; j < 8; j++) acc[i][j] += a[i] * bb[j];
        }

        // ---- coherence + online softmax ----
        float kcv[8], ksv[8];
#pragma unroll
        for (int j = 0; j < 8; j++) {
            kcv[j] = sm[KC_OFF + tx * 8 + j];
            ksv[j] = sm[KS_OFF + tx * 8 + j];
        }

#pragma unroll
        for (int i = 0; i < 8; i++) {
            float rmax = -1e30f;
#pragma unroll
            for (int j = 0; j < 8; j++) {
                float sv = acc[i][j] * scale + alp * (qc[i] * kcv[j] + qs[i] * ksv[j]);
                acc[i][j] = sv;
                rmax = fmaxf(rmax, sv);
            }
#pragma unroll
            for (int off = 8; off >= 1; off >>= 1)
                rmax = fmaxf(rmax, __shfl_xor_sync(0xffffffffu, rmax, off));

            const float mnew = fmaxf(m_i[i], rmax);
            const float corr = __expf(m_i[i] - mnew);
            m_i[i] = mnew;
            float rsum = 0.f;
#pragma unroll
            for (int j = 0; j < 8; j++) {
                const float p = __expf(acc[i][j] - mnew);
                acc[i][j] = p;
                rsum += p;
            }
#pragma unroll
            for (int off = 8; off >= 1; off >>= 1)
                rsum += __shfl_xor_sync(0xffffffffu, rsum, off);
            l_i[i] = l_i[i] * corr + rsum;
#pragma unroll
            for (int j = 0; j < 4; j++) o_acc[i][j] *= corr;
        }

        // write P to shared (row-major, vectorized)
#pragma unroll
        for (int i = 0; i < 8; i++) {
            float4 p0, p1;
            p0.x = acc[i][0]; p0.y = acc[i][1]; p0.z = acc[i][2]; p0.w = acc[i][3];
            p1.x = acc[i][4]; p1.y = acc[i][5]; p1.z = acc[i][6]; p1.w = acc[i][7];
            *(float4*)&sm[PS_OFF + (ty * 8 + i) * 132 + tx * 8]     = p0;
            *(float4*)&sm[PS_OFF + (ty * 8 + i) * 132 + tx * 8 + 4] = p1;
        }
        __syncthreads();

        // ---- PV: o[r][d] += sum_j P[r][j] * V[j][d] ----
#pragma unroll 2
        for (int j = 0; j < TK; j += 4) {
            float4 v0 = *(const float4*)&sm[VS_OFF + (j + 0) * 68 + tx * 4];
            float4 v1 = *(const float4*)&sm[VS_OFF + (j + 1) * 68 + tx * 4];
            float4 v2 = *(const float4*)&sm[VS_OFF + (j + 2) * 68 + tx * 4];
            float4 v3 = *(const float4*)&sm[VS_OFF + (j + 3) * 68 + tx * 4];
#pragma unroll
            for (int i = 0; i < 8; i++) {
                const float4 p = *(const float4*)&sm[PS_OFF + (ty * 8 + i) * 132 + j];
                o_acc[i][0] += p.x * v0.x + p.y * v1.x + p.z * v2.x + p.w * v3.x;
                o_acc[i][1] += p.x * v0.y + p.y * v1.y + p.z * v2.y + p.w * v3.y;
                o_acc[i][2] += p.x * v0.z + p.y * v1.z + p.z * v2.z + p.w * v3.z;
                o_acc[i][3] += p.x * v0.w + p.y * v1.w + p.z * v2.w + p.w * v3.w;
            }
        }
    }

    // epilogue: token-major write
    const int b = bh >> 4, h = bh & 15;
#pragma unroll
    for (int i = 0; i < 8; i++) {
        const int r = ty * 8 + i;
        const float inv = 1.f / l_i[i];
        float4 ov;
        ov.x = o_acc[i][0] * inv; ov.y = o_acc[i][1] * inv;
        ov.z = o_acc[i][2] * inv; ov.w = o_acc[i][3] * inv;
        *(float4*)&O[((size_t)b * S_LEN + q0 + r) * DMODEL + h * DK + tx * 4] = ov;
    }
}

// ============================================================================
extern "C" void kernel_launch(void* const* d_in, const int* in_sizes, int n_in,
                              void* d_out, int out_size)
{
    const float* x     = (const float*)d_in[0];
    const float* Wq    = (const float*)d_in[1];
    const float* bq    = (const float*)d_in[2];
    const float* Wk    = (const float*)d_in[3];
    const float* bk    = (const float*)d_in[4];
    const float* Wv    = (const float*)d_in[5];
    const float* bv    = (const float*)d_in[6];
    const float* Wo    = (const float*)d_in[7];
    const float* bo    = (const float*)d_in[8];
    const float* Wp    = (const float*)d_in[9];
    const float* bp    = (const float*)d_in[10];
    const float* alpha = (const float*)d_in[11];
    float* out = (float*)d_out;

    float *pQ, *pK, *pV, *pO, *pc, *ps;
    cudaGetSymbolAddress((void**)&pQ, g_Q);
    cudaGetSymbolAddress((void**)&pK, g_K);
    cudaGetSymbolAddress((void**)&pV, g_V);
    cudaGetSymbolAddress((void**)&pO, g_O);
    cudaGetSymbolAddress((void**)&pc, g_cs);
    cudaGetSymbolAddress((void**)&ps, g_sn);

    dim3 g(DMODEL / BN, NTOK / BM);   // (8, 32)

    sgemm128<2><<<g, 256>>>(x, Wq, bq, pQ, NTOK, DMODEL, DMODEL);
    sgemm128<2><<<g, 256>>>(x, Wk, bk, pK, NTOK, DMODEL, DMODEL);
    sgemm128<1><<<g, 256>>>(x, Wv, bv, pV, NTOK, DMODEL, DMODEL);
    phase_kernel<<<NTOK, 128>>>(x, Wp, bp, pc, ps);

    cudaFuncSetAttribute(attn_kernel,
                         cudaFuncAttributeMaxDynamicSharedMemorySize,
                         ATT_SMEM_BYTES);
    attn_kernel<<<dim3(S_LEN / TQ, BHALL), 256, ATT_SMEM_BYTES>>>(
        pQ, pK, pV, pc, ps, alpha, pO);

    sgemm128<0><<<g, 256>>>(pO, Wo, bo, out, NTOK, DMODEL, DMODEL);
}

// round 5
// speedup vs baseline: 1.0018x; 1.0018x over previous
#include <cuda_runtime.h>
#include <math.h>

#define S_LEN   2048
#define DMODEL  1024
#define NHEADS  16
#define DK      64
#define BATCH   2
#define NTOK    (BATCH * S_LEN)     // 4096
#define BHALL   (BATCH * NHEADS)    // 32

// ---------------- scratch (device globals; no allocation allowed) ----------
__device__ float g_Q[BHALL * DK * S_LEN];     // (bh, d, s)  dk-major
__device__ float g_K[BHALL * DK * S_LEN];     // (bh, d, s)  dk-major
__device__ float g_V[BHALL * S_LEN * DK];     // (bh, s, d)
__device__ float g_O[NTOK * DMODEL];          // token-major attention output
__device__ float g_cs[BHALL * S_LEN];
__device__ float g_sn[BHALL * S_LEN];

// ============================================================================
// SGEMM: C = A(MxK) @ B(KxN) + bias, 128x128 tiles, BK=16, 256 thr, 8x8 micro
// MODE 0: C[m*N + n]                       (token-major)
// MODE 1: C[(bh*S + s)*DK + d]             (head-major, for V)
// MODE 2: C[(bh*DK + d)*S + s]             (dk-major,  for Q/K)
// ============================================================================
#define BM 128
#define BN 128
#define BKK 16
#define LDA (BM + 4)
#define LDB (BN + 4)

template <int MODE>
__global__ void __launch_bounds__(256, 2) sgemm128(
    const float* __restrict__ A, const float* __restrict__ B,
    const float* __restrict__ bias, float* __restrict__ C,
    int M, int N, int K)
{
    __shared__ float At[2][BKK * LDA];
    __shared__ float Bs[2][BKK * LDB];

    const int tid = threadIdx.x;
    const int tx = tid & 15;
    const int ty = tid >> 4;
    const int m0 = blockIdx.y * BM;
    const int n0 = blockIdx.x * BN;

    // A tile: 128 rows x 16 cols = 512 float4 (each thread: 2)
    const int am0 = tid >> 2;            const int ak0 = (tid & 3) << 2;
    const int am1 = (tid + 256) >> 2;    const int ak1 = ((tid + 256) & 3) << 2;
    // B tile: 16 rows x 128 cols = 512 float4
    const int bk0 = tid >> 5;            const int bn0 = (tid & 31) << 2;
    const int bk1 = (tid + 256) >> 5;    const int bn1 = ((tid + 256) & 31) << 2;

    float4 ra0, ra1, rb0, rb1;

    // prologue: tile 0
    ra0 = *(const float4*)&A[(size_t)(m0 + am0) * K + ak0];
    ra1 = *(const float4*)&A[(size_t)(m0 + am1) * K + ak1];
    rb0 = *(const float4*)&B[(size_t)bk0 * N + n0 + bn0];
    rb1 = *(const float4*)&B[(size_t)bk1 * N + n0 + bn1];

    At[0][(ak0 + 0) * LDA + am0] = ra0.x;
    At[0][(ak0 + 1) * LDA + am0] = ra0.y;
    At[0][(ak0 + 2) * LDA + am0] = ra0.z;
    At[0][(ak0 + 3) * LDA + am0] = ra0.w;
    At[0][(ak1 + 0) * LDA + am1] = ra1.x;
    At[0][(ak1 + 1) * LDA + am1] = ra1.y;
    At[0][(ak1 + 2) * LDA + am1] = ra1.z;
    At[0][(ak1 + 3) * LDA + am1] = ra1.w;
    *(float4*)&Bs[0][bk0 * LDB + bn0] = rb0;
    *(float4*)&Bs[0][bk1 * LDB + bn1] = rb1;
    __syncthreads();

    float acc[8][8];
#pragma unroll
    for (int i = 0; i < 8; i++)
#pragma unroll
        for (int j = 0; j < 8; j++) acc[i][j] = 0.f;

    const int KT = K / BKK;
    for (int kt = 0; kt < KT; ++kt) {
        const int buf = kt & 1;
        if (kt + 1 < KT) {
            const int k0 = (kt + 1) * BKK;
            ra0 = *(const float4*)&A[(size_t)(m0 + am0) * K + k0 + ak0];
            ra1 = *(const float4*)&A[(size_t)(m0 + am1) * K + k0 + ak1];
            rb0 = *(const float4*)&B[(size_t)(k0 + bk0) * N + n0 + bn0];
            rb1 = *(const float4*)&B[(size_t)(k0 + bk1) * N + n0 + bn1];
        }
#pragma unroll
        for (int kk = 0; kk < BKK; ++kk) {
            float a[8], bb[8];
            *(float4*)&a[0]  = *(const float4*)&At[buf][kk * LDA + ty * 8];
            *(float4*)&a[4]  = *(const float4*)&At[buf][kk * LDA + ty * 8 + 4];
            *(float4*)&bb[0] = *(const float4*)&Bs[buf][kk * LDB + tx * 8];
            *(float4*)&bb[4] = *(const float4*)&Bs[buf][kk * LDB + tx * 8 + 4];
#pragma unroll
            for (int i = 0; i < 8; i++)
#pragma unroll
                for (int j = 0; j < 8; j++) acc[i][j] += a[i] * bb[j];
        }
        if (kt + 1 < KT) {
            const int nb = 1 - buf;
            At[nb][(ak0 + 0) * LDA + am0] = ra0.x;
            At[nb][(ak0 + 1) * LDA + am0] = ra0.y;
            At[nb][(ak0 + 2) * LDA + am0] = ra0.z;
            At[nb][(ak0 + 3) * LDA + am0] = ra0.w;
            At[nb][(ak1 + 0) * LDA + am1] = ra1.x;
            At[nb][(ak1 + 1) * LDA + am1] = ra1.y;
            At[nb][(ak1 + 2) * LDA + am1] = ra1.z;
            At[nb][(ak1 + 3) * LDA + am1] = ra1.w;
            *(float4*)&Bs[nb][bk0 * LDB + bn0] = rb0;
            *(float4*)&Bs[nb][bk1 * LDB + bn1] = rb1;
            __syncthreads();
        }
    }

    float bv[8];
#pragma unroll
    for (int j = 0; j < 8; j++) bv[j] = bias[n0 + tx * 8 + j];

#pragma unroll
    for (int i = 0; i < 8; i++) {
        const int m = m0 + ty * 8 + i;
        if (MODE == 0) {
            float4 o0, o1;
            o0.x = acc[i][0] + bv[0]; o0.y = acc[i][1] + bv[1];
            o0.z = acc[i][2] + bv[2]; o0.w = acc[i][3] + bv[3];
            o1.x = acc[i][4] + bv[4]; o1.y = acc[i][5] + bv[5];
            o1.z = acc[i][6] + bv[6]; o1.w = acc[i][7] + bv[7];
            *(float4*)&C[(size_t)m * N + n0 + tx * 8]     = o0;
            *(float4*)&C[(size_t)m * N + n0 + tx * 8 + 4] = o1;
        } else {
            const int b = m >> 11;          // m / 2048
            const int s = m & 2047;
#pragma unroll
            for (int j = 0; j < 8; j++) {
                const int n = n0 + tx * 8 + j;
                const int h = n >> 6, d = n & 63;
                const int bh = b * NHEADS + h;
                const float v = acc[i][j] + bv[j];
                if (MODE == 1)
                    C[((size_t)bh * S_LEN + s) * DK + d] = v;
                else
                    C[((size_t)bh * DK + d) * S_LEN + s] = v;
            }
        }
    }
}

// ============================================================================
// Phase kernel: phase = x @ Wp + bp ; cos/sin stored per (bh, s)
// One block (128 thr) per token; 16 heads x 8 partial threads each.
// ============================================================================
__global__ void __launch_bounds__(128) phase_kernel(
    const float* __restrict__ x, const float* __restrict__ Wp,
    const float* __restrict__ bp, float* __restrict__ cs, float* __restrict__ sn)
{
    __shared__ float xs[DMODEL];
    const int m = blockIdx.x;
    for (int i = threadIdx.x; i < DMODEL / 4; i += 128)
        *(float4*)&xs[i * 4] = *(const float4*)&x[(size_t)m * DMODEL + i * 4];
    __syncthreads();

    const int h = threadIdx.x >> 3;
    const int part = threadIdx.x & 7;
    float sum = 0.f;
    const int k0 = part * 128;
#pragma unroll 4
    for (int k = k0; k < k0 + 128; ++k) sum += xs[k] * Wp[k * NHEADS + h];
#pragma unroll
    for (int off = 4; off >= 1; off >>= 1)
        sum += __shfl_xor_sync(0xffffffffu, sum, off);

    if (part == 0) {
        const float ph = sum + bp[h];
        const int b = m >> 11, s = m & 2047;
        const int bh = b * NHEADS + h;
        float sv, cv;
        sincosf(ph, &sv, &cv);
        cs[bh * S_LEN + s] = cv;
        sn[bh * S_LEN + s] = sv;
    }
}

// ============================================================================
// Flash attention, fp32. TQ=128 queries x TK=128 keys per tile, dk=64.
// 256 thr: 16x16 grid; QK micro 8x8, PV micro 8x4. Rank-2 coherence epilogue.
// ============================================================================
#define TQ 128
#define TK 128
#define QT_OFF 0                       // Qt[64][132]
#define KT_OFF (64 * 132)              // Kt[64][132]
#define VS_OFF (KT_OFF + 64 * 132)     // Vs[128][68]
#define PS_OFF (VS_OFF + 128 * 68)     // Ps[128][132]
#define KC_OFF (PS_OFF + 128 * 132)    // kc[128]
#define KS_OFF (KC_OFF + 128)          // ks[128]
#define ATT_SMEM_FLOATS (KS_OFF + 128)
#define ATT_SMEM_BYTES (ATT_SMEM_FLOATS * 4)

__global__ void __launch_bounds__(256, 1) attn_kernel(
    const float* __restrict__ Q, const float* __restrict__ K,
    const float* __restrict__ V, const float* __restrict__ cs,
    const float* __restrict__ sn, const float* __restrict__ alpha,
    float* __restrict__ O)
{
    extern __shared__ float sm[];
    const int tid = threadIdx.x;
    const int tx = tid & 15;
    const int ty = tid >> 4;
    const int bh = blockIdx.y;
    const int q0 = blockIdx.x * TQ;
    const float scale = 0.125f;             // dk^-0.5
    const float alp = alpha[bh & (NHEADS - 1)];

    // Load Qt[k][r] (dk-major global -> coalesced rows)
#pragma unroll
    for (int i = 0; i < 8; i++) {
        const int idx = tid + i * 256;      // 0..2047
        const int k = idx >> 5;
        const int r4 = (idx & 31) << 2;
        *(float4*)&sm[QT_OFF + k * 132 + r4] =
            *(const float4*)&Q[((size_t)bh * DK + k) * S_LEN + q0 + r4];
    }

    float qc[8], qs[8];
#pragma unroll
    for (int i = 0; i < 8; i++) {
        const int r = ty * 8 + i;
        qc[i] = cs[bh * S_LEN + q0 + r];
        qs[i] = sn[bh * S_LEN + q0 + r];
    }

    float m_i[8], l_i[8], o_acc[8][4];
#pragma unroll
    for (int i = 0; i < 8; i++) {
        m_i[i] = -1e30f; l_i[i] = 0.f;
#pragma unroll
        for (int j = 0; j < 4; j++) o_acc[i][j] = 0.f;
    }

    for (int kt = 0; kt < S_LEN / TK; ++kt) {
        const int c0 = kt * TK;
        __syncthreads();   // prev iter's PV done (and Qt visible on kt=0 path below)

        // Load Kt[k][c]
#pragma unroll
        for (int i = 0; i < 8; i++) {
            const int idx = tid + i * 256;
            const int k = idx >> 5;
            const int c4 = (idx & 31) << 2;
            *(float4*)&sm[KT_OFF + k * 132 + c4] =
                *(const float4*)&K[((size_t)bh * DK + k) * S_LEN + c0 + c4];
        }
        // Load Vs[c][d]
#pragma unroll
        for (int i = 0; i < 8; i++) {
            const int idx = tid + i * 256;
            const int c = idx >> 4;
            const int d4 = (idx & 15) << 2;
            *(float4*)&sm[VS_OFF + c * 68 + d4] =
                *(const float4*)&V[((size_t)bh * S_LEN + c0 + c) * DK + d4];
        }
        if (tid < 128) {
            sm[KC_OFF + tid] = cs[bh * S_LEN + c0 + tid];
            sm[KS_OFF + tid] = sn[bh * S_LEN + c0 + tid];
        }
        __syncthreads();

        // ---- QK^T ----
        float acc[8][8];
#pragma unroll
        for (int i = 0; i < 8; i++)
#pragma unroll
            for (int j = 0; j < 8; j++) acc[i][j] = 0.f;

#pragma unroll 8
        for (int k = 0; k < DK; ++k) {
            float a[8], bb[8];
            *(float4*)&a[0]  = *(const float4*)&sm[QT_OFF + k * 132 + ty * 8];
            *(float4*)&a[4]  = *(const float4*)&sm[QT_OFF + k * 132 + ty * 8 + 4];
            *(float4*)&bb[0] = *(const float4*)&sm[KT_OFF + k * 132 + tx * 8];
            *(float4*)&bb[4] = *(const float4*)&sm[KT_OFF + k * 132 + tx * 8 + 4];
#pragma unroll
            for (int i = 0; i < 8; i++)
#pragma unroll
                for (int j = 0; j < 8; j++) acc[i][j] += a[i] * bb[j];
        }

        // ---- coherence + online softmax ----
        float kcv[8], ksv[8];
#pragma unroll
        for (int j = 0; j < 8; j++) {
            kcv[j] = sm[KC_OFF + tx * 8 + j];
            ksv[j] = sm[KS_OFF + tx * 8 + j];
        }

#pragma unroll
        for (int i = 0; i < 8; i++) {
            float rmax = -1e30f;
#pragma unroll
            for (int j = 0; j < 8; j++) {
                float sv = acc[i][j] * scale + alp * (qc[i] * kcv[j] + qs[i] * ksv[j]);
                acc[i][j] = sv;
                rmax = fmaxf(rmax, sv);
            }
#pragma unroll
            for (int off = 8; off >= 1; off >>= 1)
                rmax = fmaxf(rmax, __shfl_xor_sync(0xffffffffu, rmax, off));

            const float mnew = fmaxf(m_i[i], rmax);
            const float corr = __expf(m_i[i] - mnew);
            m_i[i] = mnew;
            float rsum = 0.f;
#pragma unroll
            for (int j = 0; j < 8; j++) {
                const float p = __expf(acc[i][j] - mnew);
                acc[i][j] = p;
                rsum += p;
            }
#pragma unroll
            for (int off = 8; off >= 1; off >>= 1)
                rsum += __shfl_xor_sync(0xffffffffu, rsum, off);
            l_i[i] = l_i[i] * corr + rsum;
#pragma unroll
            for (int j = 0; j < 4; j++) o_acc[i][j] *= corr;
        }

        // write P to shared (row-major, vectorized)
#pragma unroll
        for (int i = 0; i < 8; i++) {
            float4 p0, p1;
            p0.x = acc[i][0]; p0.y = acc[i][1]; p0.z = acc[i][2]; p0.w = acc[i][3];
            p1.x = acc[i][4]; p1.y = acc[i][5]; p1.z = acc[i][6]; p1.w = acc[i][7];
            *(float4*)&sm[PS_OFF + (ty * 8 + i) * 132 + tx * 8]     = p0;
            *(float4*)&sm[PS_OFF + (ty * 8 + i) * 132 + tx * 8 + 4] = p1;
        }
        __syncthreads();

        // ---- PV: o[r][d] += sum_j P[r][j] * V[j][d] ----
#pragma unroll 2
        for (int j = 0; j < TK; j += 4) {
            float4 v0 = *(const float4*)&sm[VS_OFF + (j + 0) * 68 + tx * 4];
            float4 v1 = *(const float4*)&sm[VS_OFF + (j + 1) * 68 + tx * 4];
            float4 v2 = *(const float4*)&sm[VS_OFF + (j + 2) * 68 + tx * 4];
            float4 v3 = *(const float4*)&sm[VS_OFF + (j + 3) * 68 + tx * 4];
#pragma unroll
            for (int i = 0; i < 8; i++) {
                const float4 p = *(const float4*)&sm[PS_OFF + (ty * 8 + i) * 132 + j];
                o_acc[i][0] += p.x * v0.x + p.y * v1.x + p.z * v2.x + p.w * v3.x;
                o_acc[i][1] += p.x * v0.y + p.y * v1.y + p.z * v2.y + p.w * v3.y;
                o_acc[i][2] += p.x * v0.z + p.y * v1.z + p.z * v2.z + p.w * v3.z;
                o_acc[i][3] += p.x * v0.w + p.y * v1.w + p.z * v2.w + p.w * v3.w;
            }
        }
    }

    // epilogue: token-major write
    const int b = bh >> 4, h = bh & 15;
#pragma unroll
    for (int i = 0; i < 8; i++) {
        const int r = ty * 8 + i;
        const float inv = 1.f / l_i[i];
        float4 ov;
        ov.x = o_acc[i][0] * inv; ov.y = o_acc[i][1] * inv;
        ov.z = o_acc[i][2] * inv; ov.w = o_acc[i][3] * inv;
        *(float4*)&O[((size_t)b * S_LEN + q0 + r) * DMODEL + h * DK + tx * 4] = ov;
    }
}

// ============================================================================
extern "C" void kernel_launch(void* const* d_in, const int* in_sizes, int n_in,
                              void* d_out, int out_size)
{
    const float* x     = (const float*)d_in[0];
    const float* Wq    = (const float*)d_in[1];
    const float* bq    = (const float*)d_in[2];
    const float* Wk    = (const float*)d_in[3];
    const float* bk    = (const float*)d_in[4];
    const float* Wv    = (const float*)d_in[5];
    const float* bv    = (const float*)d_in[6];
    const float* Wo    = (const float*)d_in[7];
    const float* bo    = (const float*)d_in[8];
    const float* Wp    = (const float*)d_in[9];
    const float* bp    = (const float*)d_in[10];
    const float* alpha = (const float*)d_in[11];
    float* out = (float*)d_out;

    float *pQ, *pK, *pV, *pO, *pc, *ps;
    cudaGetSymbolAddress((void**)&pQ, g_Q);
    cudaGetSymbolAddress((void**)&pK, g_K);
    cudaGetSymbolAddress((void**)&pV, g_V);
    cudaGetSymbolAddress((void**)&pO, g_O);
    cudaGetSymbolAddress((void**)&pc, g_cs);
    cudaGetSymbolAddress((void**)&ps, g_sn);

    dim3 g(DMODEL / BN, NTOK / BM);   // (8, 32)

    sgemm128<2><<<g, 256>>>(x, Wq, bq, pQ, NTOK, DMODEL, DMODEL);
    sgemm128<2><<<g, 256>>>(x, Wk, bk, pK, NTOK, DMODEL, DMODEL);
    sgemm128<1><<<g, 256>>>(x, Wv, bv, pV, NTOK, DMODEL, DMODEL);
    phase_kernel<<<NTOK, 128>>>(x, Wp, bp, pc, ps);

    cudaFuncSetAttribute(attn_kernel,
                         cudaFuncAttributeMaxDynamicSharedMemorySize,
                         ATT_SMEM_BYTES);
    attn_kernel<<<dim3(S_LEN / TQ, BHALL), 256, ATT_SMEM_BYTES>>>(
        pQ, pK, pV, pc, ps, alpha, pO);

    sgemm128<0><<<g, 256>>>(pO, Wo, bo, out, NTOK, DMODEL, DMODEL);
}

// round 6
// speedup vs baseline: 1.4331x; 1.4305x over previous
#include <cuda_runtime.h>
#include <cuda_bf16.h>
#include <math.h>

#define S_LEN   2048
#define DMODEL  1024
#define NHEADS  16
#define DK      64
#define BATCH   2
#define NTOK    (BATCH * S_LEN)     // 4096
#define BHALL   (BATCH * NHEADS)    // 32

// ---------------- scratch (device globals; no allocation allowed) ----------
__device__ float g_Q[BHALL * DK * S_LEN];     // (bh, d, s)  dk-major
__device__ float g_K[BHALL * DK * S_LEN];     // (bh, d, s)  dk-major
__device__ float g_V[BHALL * S_LEN * DK];     // (bh, s, d)
__device__ float g_O[NTOK * DMODEL];          // token-major attention output
__device__ float g_cs[BHALL * S_LEN];
__device__ float g_sn[BHALL * S_LEN];

// ============================================================================
// Warp-MMA helpers (legacy mma.sync path, bf16 x bf16 -> f32)
// ============================================================================
__device__ __forceinline__ unsigned sptr(const void* p) {
    return (unsigned)__cvta_generic_to_shared(p);
}

__device__ __forceinline__ void ldsm_x4(unsigned r[4], unsigned sa) {
    asm volatile("ldmatrix.sync.aligned.m8n8.x4.shared.b16 {%0,%1,%2,%3}, [%4];"
                 : "=r"(r[0]), "=r"(r[1]), "=r"(r[2]), "=r"(r[3]) : "r"(sa));
}
__device__ __forceinline__ void ldsm_x4t(unsigned r[4], unsigned sa) {
    asm volatile("ldmatrix.sync.aligned.m8n8.x4.trans.shared.b16 {%0,%1,%2,%3}, [%4];"
                 : "=r"(r[0]), "=r"(r[1]), "=r"(r[2]), "=r"(r[3]) : "r"(sa));
}
__device__ __forceinline__ void mma_bf16(float c[4], const unsigned a[4], const unsigned b[2]) {
    asm volatile(
        "mma.sync.aligned.m16n8k16.row.col.f32.bf16.bf16.f32 "
        "{%0,%1,%2,%3}, {%4,%5,%6,%7}, {%8,%9}, {%0,%1,%2,%3};"
        : "+f"(c[0]), "+f"(c[1]), "+f"(c[2]), "+f"(c[3])
        : "r"(a[0]), "r"(a[1]), "r"(a[2]), "r"(a[3]), "r"(b[0]), "r"(b[1]));
}

// float4 -> (hi bf16 x4 as 2x u32) + (lo bf16 x4 as 2x u32)
__device__ __forceinline__ void f4_to_hilo(const float4 v,
    unsigned& h01, unsigned& h23, unsigned& l01, unsigned& l23)
{
    __nv_bfloat16 hx = __float2bfloat16(v.x);
    __nv_bfloat16 hy = __float2bfloat16(v.y);
    __nv_bfloat16 hz = __float2bfloat16(v.z);
    __nv_bfloat16 hw = __float2bfloat16(v.w);
    __nv_bfloat16 lx = __float2bfloat16(v.x - __bfloat162float(hx));
    __nv_bfloat16 ly = __float2bfloat16(v.y - __bfloat162float(hy));
    __nv_bfloat16 lz = __float2bfloat16(v.z - __bfloat162float(hz));
    __nv_bfloat16 lw = __float2bfloat16(v.w - __bfloat162float(hw));
    __nv_bfloat162 t;
    t.x = hx; t.y = hy; h01 = *reinterpret_cast<unsigned*>(&t);
    t.x = hz; t.y = hw; h23 = *reinterpret_cast<unsigned*>(&t);
    t.x = lx; t.y = ly; l01 = *reinterpret_cast<unsigned*>(&t);
    t.x = lz; t.y = lw; l23 = *reinterpret_cast<unsigned*>(&t);
}

// ============================================================================
// Tensor-core GEMM: C = A(MxK fp32) @ B(KxN fp32) + bias, via bf16 hi/lo split.
// CTA tile 128x128, K-chunk 32, 256 thr = 8 warps (4m x 2n), warp tile 32x64.
// MODE 0: C[m*N + n]                (token-major)
// MODE 1: C[(bh*S + s)*DK + d]      (head-major, V)
// MODE 2: C[(bh*DK + d)*S + s]      (dk-major,  Q/K)
// ============================================================================
#define ASTR 40            // A smem row stride (bf16), [128][32] + pad
#define BSTR 136           // B smem row stride (bf16), [32][128] + pad
#define A_ELEMS (128 * ASTR)          // 5120
#define B_ELEMS (32 * BSTR)           // 4352
#define BUF_ELEMS (2 * A_ELEMS + 2 * B_ELEMS)   // 18944 bf16 per buffer
#define MMA_SMEM_BYTES (2 * BUF_ELEMS * 2)      // 75776 B

template <int MODE>
__global__ void __launch_bounds__(256) gemm_mma(
    const float* __restrict__ A, const float* __restrict__ B,
    const float* __restrict__ bias, float* __restrict__ C,
    int M, int N, int K)
{
    extern __shared__ __nv_bfloat16 smb[];
    const int tid  = threadIdx.x;
    const int lane = tid & 31;
    const int warp = tid >> 5;
    const int wm = (warp >> 1) * 32;
    const int wn = (warp & 1) * 64;
    const int m0 = blockIdx.y * 128;
    const int n0 = blockIdx.x * 128;

    // staging indices (4 float4 each for A and B per thread)
    int arow[4], acol[4], brow[4], bcol[4];
#pragma unroll
    for (int j = 0; j < 4; j++) {
        const int idx = tid + j * 256;       // 0..1023
        arow[j] = idx >> 3;  acol[j] = (idx & 7) << 2;    // A: 128 x 32
        brow[j] = idx >> 5;  bcol[j] = (idx & 31) << 2;   // B: 32 x 128
    }

    float4 pa[4], pb[4];

    // ---- prologue: load + stage k-chunk 0 into buffer 0 ----
#pragma unroll
    for (int j = 0; j < 4; j++) {
        pa[j] = *(const float4*)&A[(size_t)(m0 + arow[j]) * K + acol[j]];
        pb[j] = *(const float4*)&B[(size_t)brow[j] * N + n0 + bcol[j]];
    }
    {
        __nv_bfloat16* Ah = smb;
        __nv_bfloat16* Al = Ah + A_ELEMS;
        __nv_bfloat16* Bh = smb + 2 * A_ELEMS;
        __nv_bfloat16* Bl = Bh + B_ELEMS;
#pragma unroll
        for (int j = 0; j < 4; j++) {
            unsigned h01, h23, l01, l23;
            f4_to_hilo(pa[j], h01, h23, l01, l23);
            *reinterpret_cast<uint2*>(&Ah[arow[j] * ASTR + acol[j]]) = make_uint2(h01, h23);
            *reinterpret_cast<uint2*>(&Al[arow[j] * ASTR + acol[j]]) = make_uint2(l01, l23);
            f4_to_hilo(pb[j], h01, h23, l01, l23);
            *reinterpret_cast<uint2*>(&Bh[brow[j] * BSTR + bcol[j]]) = make_uint2(h01, h23);
            *reinterpret_cast<uint2*>(&Bl[brow[j] * BSTR + bcol[j]]) = make_uint2(l01, l23);
        }
    }
    __syncthreads();

    float acc[2][8][4];
#pragma unroll
    for (int mt = 0; mt < 2; mt++)
#pragma unroll
        for (int nt = 0; nt < 8; nt++)
#pragma unroll
            for (int e = 0; e < 4; e++) acc[mt][nt][e] = 0.f;

    const int KT = K / 32;
    for (int kt = 0; kt < KT; ++kt) {
        const int buf = kt & 1;
        if (kt + 1 < KT) {
            const int k0 = (kt + 1) * 32;
#pragma unroll
            for (int j = 0; j < 4; j++) {
                pa[j] = *(const float4*)&A[(size_t)(m0 + arow[j]) * K + k0 + acol[j]];
                pb[j] = *(const float4*)&B[(size_t)(k0 + brow[j]) * N + n0 + bcol[j]];
            }
        }

        const __nv_bfloat16* Ah = smb + buf * BUF_ELEMS;
        const __nv_bfloat16* Bh = smb + buf * BUF_ELEMS + 2 * A_ELEMS;

#pragma unroll
        for (int kk = 0; kk < 32; kk += 16) {
            // A fragments (hi/lo), 2 m-tiles
            unsigned afh[2][4], afl[2][4];
#pragma unroll
            for (int mt = 0; mt < 2; mt++) {
                unsigned sa = sptr(&Ah[(wm + mt * 16 + (lane & 15)) * ASTR
                                       + kk + ((lane >> 4) << 3)]);
                ldsm_x4(afh[mt], sa);
                ldsm_x4(afl[mt], sa + A_ELEMS * 2);   // Al is A_ELEMS bf16 after Ah
            }
            // B fragments (hi/lo), 8 n-tiles via 4 x4.trans loads
            unsigned bfh[8][2], bfl[8][2];
#pragma unroll
            for (int np = 0; np < 4; np++) {
                unsigned sb = sptr(&Bh[(kk + (lane & 15)) * BSTR
                                       + wn + np * 16 + ((lane >> 4) << 3)]);
                unsigned r[4];
                ldsm_x4t(r, sb);
                bfh[2 * np][0] = r[0]; bfh[2 * np][1] = r[1];
                bfh[2 * np + 1][0] = r[2]; bfh[2 * np + 1][1] = r[3];
                ldsm_x4t(r, sb + B_ELEMS * 2);        // Bl is B_ELEMS bf16 after Bh
                bfl[2 * np][0] = r[0]; bfl[2 * np][1] = r[1];
                bfl[2 * np + 1][0] = r[2]; bfl[2 * np + 1][1] = r[3];
            }
            // 3-term split MMA
#pragma unroll
            for (int mt = 0; mt < 2; mt++)
#pragma unroll
                for (int nt = 0; nt < 8; nt++) {
                    mma_bf16(acc[mt][nt], afh[mt], bfh[nt]);
                    mma_bf16(acc[mt][nt], afh[mt], bfl[nt]);
                    mma_bf16(acc[mt][nt], afl[mt], bfh[nt]);
                }
        }

        if (kt + 1 < KT) {
            const int nb = 1 - buf;
            __nv_bfloat16* nAh = smb + nb * BUF_ELEMS;
            __nv_bfloat16* nAl = nAh + A_ELEMS;
            __nv_bfloat16* nBh = smb + nb * BUF_ELEMS + 2 * A_ELEMS;
            __nv_bfloat16* nBl = nBh + B_ELEMS;
#pragma unroll
            for (int j = 0; j < 4; j++) {
                unsigned h01, h23, l01, l23;
                f4_to_hilo(pa[j], h01, h23, l01, l23);
                *reinterpret_cast<uint2*>(&nAh[arow[j] * ASTR + acol[j]]) = make_uint2(h01, h23);
                *reinterpret_cast<uint2*>(&nAl[arow[j] * ASTR + acol[j]]) = make_uint2(l01, l23);
                f4_to_hilo(pb[j], h01, h23, l01, l23);
                *reinterpret_cast<uint2*>(&nBh[brow[j] * BSTR + bcol[j]]) = make_uint2(h01, h23);
                *reinterpret_cast<uint2*>(&nBl[brow[j] * BSTR + bcol[j]]) = make_uint2(l01, l23);
            }
            __syncthreads();
        }
    }

    // ---- epilogue: acc mapping m16n8: c0,c1 -> row lane>>2, cols (lane&3)*2,+1
    //                              c2,c3 -> row +8
#pragma unroll
    for (int mt = 0; mt < 2; mt++) {
        const int r0 = m0 + wm + mt * 16 + (lane >> 2);
#pragma unroll
        for (int nt = 0; nt < 8; nt++) {
            const int c = n0 + wn + nt * 8 + ((lane & 3) << 1);
            const float b0v = bias[c], b1v = bias[c + 1];
            const float v00 = acc[mt][nt][0] + b0v;
            const float v01 = acc[mt][nt][1] + b1v;
            const float v10 = acc[mt][nt][2] + b0v;
            const float v11 = acc[mt][nt][3] + b1v;
            if (MODE == 0) {
                float2 w0 = make_float2(v00, v01);
                float2 w1 = make_float2(v10, v11);
                *(float2*)&C[(size_t)r0 * N + c]       = w0;
                *(float2*)&C[(size_t)(r0 + 8) * N + c] = w1;
            } else {
                const int b = r0 >> 11;               // token 128-tile never crosses 2048
                const int s = r0 & 2047;
                const int h = c >> 6, d = c & 63;
                const int bh = b * NHEADS + h;
                if (MODE == 1) {
                    float2 w0 = make_float2(v00, v01);
                    float2 w1 = make_float2(v10, v11);
                    *(float2*)&C[((size_t)bh * S_LEN + s) * DK + d]     = w0;
                    *(float2*)&C[((size_t)bh * S_LEN + s + 8) * DK + d] = w1;
                } else {
                    C[((size_t)bh * DK + d)     * S_LEN + s]     = v00;
                    C[((size_t)bh * DK + d + 1) * S_LEN + s]     = v01;
                    C[((size_t)bh * DK + d)     * S_LEN + s + 8] = v10;
                    C[((size_t)bh * DK + d + 1) * S_LEN + s + 8] = v11;
                }
            }
        }
    }
}

// ============================================================================
// Phase kernel v2: warp-per-token, Wp transposed in smem (conflict-free LDS).
// 512 blocks x 256 thr; block stages WpT[16][1032] (66 KB), 8 tokens/block.
// ============================================================================
#define WPT_STRIDE 1032
#define PHASE_SMEM_BYTES (16 * WPT_STRIDE * 4)   // 66048

__global__ void __launch_bounds__(256) phase_kernel2(
    const float* __restrict__ x, const float* __restrict__ Wp,
    const float* __restrict__ bp, float* __restrict__ cs, float* __restrict__ sn)
{
    extern __shared__ float WpT[];
    const int tid = threadIdx.x;
    // stage Wp[k][h] -> WpT[h][k]
    for (int idx = tid; idx < DMODEL * NHEADS; idx += 256) {
        const int k = idx >> 4, h = idx & 15;
        WpT[h * WPT_STRIDE + k] = Wp[idx];
    }
    __syncthreads();

    const int lane = tid & 31;
    const int warp = tid >> 5;
    const int t = blockIdx.x * 8 + warp;          // token 0..4095

    float acc[NHEADS];
#pragma unroll
    for (int h = 0; h < NHEADS; h++) acc[h] = 0.f;

#pragma unroll 4
    for (int i = 0; i < 32; ++i) {
        const int k = i * 32 + lane;
        const float xv = x[(size_t)t * DMODEL + k];
#pragma unroll
        for (int h = 0; h < NHEADS; h++)
            acc[h] += xv * WpT[h * WPT_STRIDE + k];
    }

    float myph = 0.f;
#pragma unroll
    for (int h = 0; h < NHEADS; h++) {
        float v = acc[h];
#pragma unroll
        for (int off = 16; off >= 1; off >>= 1)
            v += __shfl_xor_sync(0xffffffffu, v, off);
        if (lane == h) myph = v;
    }

    if (lane < NHEADS) {
        const float ph = myph + bp[lane];
        const int b = t >> 11, s = t & 2047;
        const int bh = b * NHEADS + lane;
        float sv, cv;
        sincosf(ph, &sv, &cv);
        cs[bh * S_LEN + s] = cv;
        sn[bh * S_LEN + s] = sv;
    }
}

// ============================================================================
// Flash attention, fp32 (unchanged from R5-passing version).
// ============================================================================
#define TQ 128
#define TK 128
#define QT_OFF 0                       // Qt[64][132]
#define KT_OFF (64 * 132)              // Kt[64][132]
#define VS_OFF (KT_OFF + 64 * 132)     // Vs[128][68]
#define PS_OFF (VS_OFF + 128 * 68)     // Ps[128][132]
#define KC_OFF (PS_OFF + 128 * 132)    // kc[128]
#define KS_OFF (KC_OFF + 128)          // ks[128]
#define ATT_SMEM_FLOATS (KS_OFF + 128)
#define ATT_SMEM_BYTES (ATT_SMEM_FLOATS * 4)

__global__ void __launch_bounds__(256, 1) attn_kernel(
    const float* __restrict__ Q, const float* __restrict__ K,
    const float* __restrict__ V, const float* __restrict__ cs,
    const float* __restrict__ sn, const float* __restrict__ alpha,
    float* __restrict__ O)
{
    extern __shared__ float sm[];
    const int tid = threadIdx.x;
    const int tx = tid & 15;
    const int ty = tid >> 4;
    const int bh = blockIdx.y;
    const int q0 = blockIdx.x * TQ;
    const float scale = 0.125f;             // dk^-0.5
    const float alp = alpha[bh & (NHEADS - 1)];

#pragma unroll
    for (int i = 0; i < 8; i++) {
        const int idx = tid + i * 256;
        const int k = idx >> 5;
        const int r4 = (idx & 31) << 2;
        *(float4*)&sm[QT_OFF + k * 132 + r4] =
            *(const float4*)&Q[((size_t)bh * DK + k) * S_LEN + q0 + r4];
    }

    float qc[8], qs[8];
#pragma unroll
    for (int i = 0; i < 8; i++) {
        const int r = ty * 8 + i;
        qc[i] = cs[bh * S_LEN + q0 + r];
        qs[i] = sn[bh * S_LEN + q0 + r];
    }

    float m_i[8], l_i[8], o_acc[8][4];
#pragma unroll
    for (int i = 0; i < 8; i++) {
        m_i[i] = -1e30f; l_i[i] = 0.f;
#pragma unroll
        for (int j = 0; j < 4; j++) o_acc[i][j] = 0.f;
    }

    for (int kt = 0; kt < S_LEN / TK; ++kt) {
        const int c0 = kt * TK;
        __syncthreads();

#pragma unroll
        for (int i = 0; i < 8; i++) {
            const int idx = tid + i * 256;
            const int k = idx >> 5;
            const int c4 = (idx & 31) << 2;
            *(float4*)&sm[KT_OFF + k * 132 + c4] =
                *(const float4*)&K[((size_t)bh * DK + k) * S_LEN + c0 + c4];
        }
#pragma unroll
        for (int i = 0; i < 8; i++) {
            const int idx = tid + i * 256;
            const int c = idx >> 4;
            const int d4 = (idx & 15) << 2;
            *(float4*)&sm[VS_OFF + c * 68 + d4] =
                *(const float4*)&V[((size_t)bh * S_LEN + c0 + c) * DK + d4];
        }
        if (tid < 128) {
            sm[KC_OFF + tid] = cs[bh * S_LEN + c0 + tid];
            sm[KS_OFF + tid] = sn[bh * S_LEN + c0 + tid];
        }
        __syncthreads();

        float acc[8][8];
#pragma unroll
        for (int i = 0; i < 8; i++)
#pragma unroll
            for (int j = 0; j < 8; j++) acc[i][j] = 0.f;

#pragma unroll 8
        for (int k = 0; k < DK; ++k) {
            float a[8], bb[8];
            *(float4*)&a[0]  = *(const float4*)&sm[QT_OFF + k * 132 + ty * 8];
            *(float4*)&a[4]  = *(const float4*)&sm[QT_OFF + k * 132 + ty * 8 + 4];
            *(float4*)&bb[0] = *(const float4*)&sm[KT_OFF + k * 132 + tx * 8];
            *(float4*)&bb[4] = *(const float4*)&sm[KT_OFF + k * 132 + tx * 8 + 4];
#pragma unroll
            for (int i = 0; i < 8; i++)
#pragma unroll
                for (int j = 0; j < 8; j++) acc[i][j] += a[i] * bb[j];
        }

        float kcv[8], ksv[8];
#pragma unroll
        for (int j = 0; j < 8; j++) {
            kcv[j] = sm[KC_OFF + tx * 8 + j];
            ksv[j] = sm[KS_OFF + tx * 8 + j];
        }

#pragma unroll
        for (int i = 0; i < 8; i++) {
            float rmax = -1e30f;
#pragma unroll
            for (int j = 0; j < 8; j++) {
                float sv = acc[i][j] * scale + alp * (qc[i] * kcv[j] + qs[i] * ksv[j]);
                acc[i][j] = sv;
                rmax = fmaxf(rmax, sv);
            }
#pragma unroll
            for (int off = 8; off >= 1; off >>= 1)
                rmax = fmaxf(rmax, __shfl_xor_sync(0xffffffffu, rmax, off));

            const float mnew = fmaxf(m_i[i], rmax);
            const float corr = __expf(m_i[i] - mnew);
            m_i[i] = mnew;
            float rsum = 0.f;
#pragma unroll
            for (int j = 0; j < 8; j++) {
                const float p = __expf(acc[i][j] - mnew);
                acc[i][j] = p;
                rsum += p;
            }
#pragma unroll
            for (int off = 8; off >= 1; off >>= 1)
                rsum += __shfl_xor_sync(0xffffffffu, rsum, off);
            l_i[i] = l_i[i] * corr + rsum;
#pragma unroll
            for (int j = 0; j < 4; j++) o_acc[i][j] *= corr;
        }

#pragma unroll
        for (int i = 0; i < 8; i++) {
            float4 p0, p1;
            p0.x = acc[i][0]; p0.y = acc[i][1]; p0.z = acc[i][2]; p0.w = acc[i][3];
            p1.x = acc[i][4]; p1.y = acc[i][5]; p1.z = acc[i][6]; p1.w = acc[i][7];
            *(float4*)&sm[PS_OFF + (ty * 8 + i) * 132 + tx * 8]     = p0;
            *(float4*)&sm[PS_OFF + (ty * 8 + i) * 132 + tx * 8 + 4] = p1;
        }
        __syncthreads();

#pragma unroll 2
        for (int j = 0; j < TK; j += 4) {
            float4 v0 = *(const float4*)&sm[VS_OFF + (j + 0) * 68 + tx * 4];
            float4 v1 = *(const float4*)&sm[VS_OFF + (j + 1) * 68 + tx * 4];
            float4 v2 = *(const float4*)&sm[VS_OFF + (j + 2) * 68 + tx * 4];
            float4 v3 = *(const float4*)&sm[VS_OFF + (j + 3) * 68 + tx * 4];
#pragma unroll
            for (int i = 0; i < 8; i++) {
                const float4 p = *(const float4*)&sm[PS_OFF + (ty * 8 + i) * 132 + j];
                o_acc[i][0] += p.x * v0.x + p.y * v1.x + p.z * v2.x + p.w * v3.x;
                o_acc[i][1] += p.x * v0.y + p.y * v1.y + p.z * v2.y + p.w * v3.y;
                o_acc[i][2] += p.x * v0.z + p.y * v1.z + p.z * v2.z + p.w * v3.z;
                o_acc[i][3] += p.x * v0.w + p.y * v1.w + p.z * v2.w + p.w * v3.w;
            }
        }
    }

    const int b = bh >> 4, h = bh & 15;
#pragma unroll
    for (int i = 0; i < 8; i++) {
        const int r = ty * 8 + i;
        const float inv = 1.f / l_i[i];
        float4 ov;
        ov.x = o_acc[i][0] * inv; ov.y = o_acc[i][1] * inv;
        ov.z = o_acc[i][2] * inv; ov.w = o_acc[i][3] * inv;
        *(float4*)&O[((size_t)b * S_LEN + q0 + r) * DMODEL + h * DK + tx * 4] = ov;
    }
}

// ============================================================================
extern "C" void kernel_launch(void* const* d_in, const int* in_sizes, int n_in,
                              void* d_out, int out_size)
{
    const float* x     = (const float*)d_in[0];
    const float* Wq    = (const float*)d_in[1];
    const float* bq    = (const float*)d_in[2];
    const float* Wk    = (const float*)d_in[3];
    const float* bk    = (const float*)d_in[4];
    const float* Wv    = (const float*)d_in[5];
    const float* bv    = (const float*)d_in[6];
    const float* Wo    = (const float*)d_in[7];
    const float* bo    = (const float*)d_in[8];
    const float* Wp    = (const float*)d_in[9];
    const float* bp    = (const float*)d_in[10];
    const float* alpha = (const float*)d_in[11];
    float* out = (float*)d_out;

    float *pQ, *pK, *pV, *pO, *pc, *ps;
    cudaGetSymbolAddress((void**)&pQ, g_Q);
    cudaGetSymbolAddress((void**)&pK, g_K);
    cudaGetSymbolAddress((void**)&pV, g_V);
    cudaGetSymbolAddress((void**)&pO, g_O);
    cudaGetSymbolAddress((void**)&pc, g_cs);
    cudaGetSymbolAddress((void**)&ps, g_sn);

    cudaFuncSetAttribute(gemm_mma<0>, cudaFuncAttributeMaxDynamicSharedMemorySize, MMA_SMEM_BYTES);
    cudaFuncSetAttribute(gemm_mma<1>, cudaFuncAttributeMaxDynamicSharedMemorySize, MMA_SMEM_BYTES);
    cudaFuncSetAttribute(gemm_mma<2>, cudaFuncAttributeMaxDynamicSharedMemorySize, MMA_SMEM_BYTES);
    cudaFuncSetAttribute(phase_kernel2, cudaFuncAttributeMaxDynamicSharedMemorySize, PHASE_SMEM_BYTES);
    cudaFuncSetAttribute(attn_kernel, cudaFuncAttributeMaxDynamicSharedMemorySize, ATT_SMEM_BYTES);

    dim3 g(DMODEL / 128, NTOK / 128);   // (8, 32)

    gemm_mma<2><<<g, 256, MMA_SMEM_BYTES>>>(x, Wq, bq, pQ, NTOK, DMODEL, DMODEL);
    gemm_mma<2><<<g, 256, MMA_SMEM_BYTES>>>(x, Wk, bk, pK, NTOK, DMODEL, DMODEL);
    gemm_mma<1><<<g, 256, MMA_SMEM_BYTES>>>(x, Wv, bv, pV, NTOK, DMODEL, DMODEL);
    phase_kernel2<<<NTOK / 8, 256, PHASE_SMEM_BYTES>>>(x, Wp, bp, pc, ps);

    attn_kernel<<<dim3(S_LEN / TQ, BHALL), 256, ATT_SMEM_BYTES>>>(
        pQ, pK, pV, pc, ps, alpha, pO);

    gemm_mma<0><<<g, 256, MMA_SMEM_BYTES>>>(pO, Wo, bo, out, NTOK, DMODEL, DMODEL);
}

// round 7
// speedup vs baseline: 2.6790x; 1.8694x over previous
#include <cuda_runtime.h>
#include <cuda_bf16.h>
#include <math.h>

#define S_LEN   2048
#define DMODEL  1024
#define NHEADS  16
#define DK      64
#define BATCH   2
#define NTOK    (BATCH * S_LEN)     // 4096
#define BHALL   (BATCH * NHEADS)    // 32

// ---------------- scratch (device globals; no allocation allowed) ----------
__device__ __nv_bfloat16 g_Qh[BHALL * S_LEN * DK];
__device__ __nv_bfloat16 g_Ql[BHALL * S_LEN * DK];
__device__ __nv_bfloat16 g_Kh[BHALL * S_LEN * DK];
__device__ __nv_bfloat16 g_Kl[BHALL * S_LEN * DK];
__device__ __nv_bfloat16 g_Vh[BHALL * S_LEN * DK];
__device__ __nv_bfloat16 g_Vl[BHALL * S_LEN * DK];
__device__ float g_O[NTOK * DMODEL];
__device__ float g_cs[BHALL * S_LEN];
__device__ float g_sn[BHALL * S_LEN];

// ============================================================================
// MMA / ldmatrix / cp.async helpers
// ============================================================================
__device__ __forceinline__ unsigned sptr(const void* p) {
    return (unsigned)__cvta_generic_to_shared(p);
}
__device__ __forceinline__ void ldsm_x4(unsigned r[4], unsigned sa) {
    asm volatile("ldmatrix.sync.aligned.m8n8.x4.shared.b16 {%0,%1,%2,%3}, [%4];"
                 : "=r"(r[0]), "=r"(r[1]), "=r"(r[2]), "=r"(r[3]) : "r"(sa));
}
__device__ __forceinline__ void ldsm_x4t(unsigned r[4], unsigned sa) {
    asm volatile("ldmatrix.sync.aligned.m8n8.x4.trans.shared.b16 {%0,%1,%2,%3}, [%4];"
                 : "=r"(r[0]), "=r"(r[1]), "=r"(r[2]), "=r"(r[3]) : "r"(sa));
}
__device__ __forceinline__ void mma_bf16(float c[4], const unsigned a[4], const unsigned b[2]) {
    asm volatile(
        "mma.sync.aligned.m16n8k16.row.col.f32.bf16.bf16.f32 "
        "{%0,%1,%2,%3}, {%4,%5,%6,%7}, {%8,%9}, {%0,%1,%2,%3};"
        : "+f"(c[0]), "+f"(c[1]), "+f"(c[2]), "+f"(c[3])
        : "r"(a[0]), "r"(a[1]), "r"(a[2]), "r"(a[3]), "r"(b[0]), "r"(b[1]));
}
__device__ __forceinline__ void cpa16(unsigned d, const void* s) {
    asm volatile("cp.async.cg.shared.global [%0], [%1], 16;" :: "r"(d), "l"(s));
}
__device__ __forceinline__ void cp_commit() {
    asm volatile("cp.async.commit_group;");
}
template <int N> __device__ __forceinline__ void cp_wait() {
    asm volatile("cp.async.wait_group %0;" :: "n"(N));
}
// pack 2 floats -> bf16x2 u32, element0 = e0 (low half)
__device__ __forceinline__ unsigned packbf(float e0, float e1) {
    unsigned r;
    asm("cvt.rn.bf16x2.f32 %0, %1, %2;" : "=r"(r) : "f"(e1), "f"(e0));
    return r;
}
__device__ __forceinline__ void hilo2(float e0, float e1, unsigned& hi, unsigned& lo) {
    hi = packbf(e0, e1);
    const float f0 = __uint_as_float(hi << 16);
    const float f1 = __uint_as_float(hi & 0xffff0000u);
    lo = packbf(e0 - f0, e1 - f1);
}

// float4 -> (hi bf16 x4 as 2x u32) + (lo bf16 x4 as 2x u32)
__device__ __forceinline__ void f4_to_hilo(const float4 v,
    unsigned& h01, unsigned& h23, unsigned& l01, unsigned& l23)
{
    hilo2(v.x, v.y, h01, l01);
    hilo2(v.z, v.w, h23, l23);
}

// ============================================================================
// Tensor-core GEMM: 128x128 tiles, K-chunk 32, 256 thr, bf16 hi/lo 3-term.
// MODE 0: fp32 C[m*N + n]                           (token-major, final proj)
// MODE 1: bf16 hi/lo head-major Ch/Cl[(bh*S+s)*64+d], v=(acc+bias)*scl (QKV)
// ============================================================================
#define ASTR 40
#define BSTR 136
#define A_ELEMS (128 * ASTR)
#define B_ELEMS (32 * BSTR)
#define BUF_ELEMS (2 * A_ELEMS + 2 * B_ELEMS)
#define MMA_SMEM_BYTES (2 * BUF_ELEMS * 2)

template <int MODE>
__global__ void __launch_bounds__(256) gemm_mma(
    const float* __restrict__ A, const float* __restrict__ B,
    const float* __restrict__ bias, float* __restrict__ C,
    __nv_bfloat16* __restrict__ Ch, __nv_bfloat16* __restrict__ Cl,
    float scl, int M, int N, int K)
{
    extern __shared__ __nv_bfloat16 smb[];
    const int tid  = threadIdx.x;
    const int lane = tid & 31;
    const int warp = tid >> 5;
    const int wm = (warp >> 1) * 32;
    const int wn = (warp & 1) * 64;
    const int m0 = blockIdx.y * 128;
    const int n0 = blockIdx.x * 128;

    int arow[4], acol[4], brow[4], bcol[4];
#pragma unroll
    for (int j = 0; j < 4; j++) {
        const int idx = tid + j * 256;
        arow[j] = idx >> 3;  acol[j] = (idx & 7) << 2;
        brow[j] = idx >> 5;  bcol[j] = (idx & 31) << 2;
    }

    float4 pa[4], pb[4];
#pragma unroll
    for (int j = 0; j < 4; j++) {
        pa[j] = *(const float4*)&A[(size_t)(m0 + arow[j]) * K + acol[j]];
        pb[j] = *(const float4*)&B[(size_t)brow[j] * N + n0 + bcol[j]];
    }
    {
        __nv_bfloat16* Ah = smb;
        __nv_bfloat16* Al = Ah + A_ELEMS;
        __nv_bfloat16* Bh = smb + 2 * A_ELEMS;
        __nv_bfloat16* Bl = Bh + B_ELEMS;
#pragma unroll
        for (int j = 0; j < 4; j++) {
            unsigned h01, h23, l01, l23;
            f4_to_hilo(pa[j], h01, h23, l01, l23);
            *reinterpret_cast<uint2*>(&Ah[arow[j] * ASTR + acol[j]]) = make_uint2(h01, h23);
            *reinterpret_cast<uint2*>(&Al[arow[j] * ASTR + acol[j]]) = make_uint2(l01, l23);
            f4_to_hilo(pb[j], h01, h23, l01, l23);
            *reinterpret_cast<uint2*>(&Bh[brow[j] * BSTR + bcol[j]]) = make_uint2(h01, h23);
            *reinterpret_cast<uint2*>(&Bl[brow[j] * BSTR + bcol[j]]) = make_uint2(l01, l23);
        }
    }
    __syncthreads();

    float acc[2][8][4];
#pragma unroll
    for (int mt = 0; mt < 2; mt++)
#pragma unroll
        for (int nt = 0; nt < 8; nt++)
#pragma unroll
            for (int e = 0; e < 4; e++) acc[mt][nt][e] = 0.f;

    const int KT = K / 32;
    for (int kt = 0; kt < KT; ++kt) {
        const int buf = kt & 1;
        if (kt + 1 < KT) {
            const int k0 = (kt + 1) * 32;
#pragma unroll
            for (int j = 0; j < 4; j++) {
                pa[j] = *(const float4*)&A[(size_t)(m0 + arow[j]) * K + k0 + acol[j]];
                pb[j] = *(const float4*)&B[(size_t)(k0 + brow[j]) * N + n0 + bcol[j]];
            }
        }

        const __nv_bfloat16* Ah = smb + buf * BUF_ELEMS;
        const __nv_bfloat16* Bh = smb + buf * BUF_ELEMS + 2 * A_ELEMS;

#pragma unroll
        for (int kk = 0; kk < 32; kk += 16) {
            unsigned afh[2][4], afl[2][4];
#pragma unroll
            for (int mt = 0; mt < 2; mt++) {
                unsigned sa = sptr(&Ah[(wm + mt * 16 + (lane & 15)) * ASTR
                                       + kk + ((lane >> 4) << 3)]);
                ldsm_x4(afh[mt], sa);
                ldsm_x4(afl[mt], sa + A_ELEMS * 2);
            }
            unsigned bfh[8][2], bfl[8][2];
#pragma unroll
            for (int np = 0; np < 4; np++) {
                unsigned sb = sptr(&Bh[(kk + (lane & 15)) * BSTR
                                       + wn + np * 16 + ((lane >> 4) << 3)]);
                unsigned r[4];
                ldsm_x4t(r, sb);
                bfh[2 * np][0] = r[0]; bfh[2 * np][1] = r[1];
                bfh[2 * np + 1][0] = r[2]; bfh[2 * np + 1][1] = r[3];
                ldsm_x4t(r, sb + B_ELEMS * 2);
                bfl[2 * np][0] = r[0]; bfl[2 * np][1] = r[1];
                bfl[2 * np + 1][0] = r[2]; bfl[2 * np + 1][1] = r[3];
            }
#pragma unroll
            for (int mt = 0; mt < 2; mt++)
#pragma unroll
                for (int nt = 0; nt < 8; nt++) {
                    mma_bf16(acc[mt][nt], afh[mt], bfh[nt]);
                    mma_bf16(acc[mt][nt], afh[mt], bfl[nt]);
                    mma_bf16(acc[mt][nt], afl[mt], bfh[nt]);
                }
        }

        if (kt + 1 < KT) {
            const int nb = 1 - buf;
            __nv_bfloat16* nAh = smb + nb * BUF_ELEMS;
            __nv_bfloat16* nAl = nAh + A_ELEMS;
            __nv_bfloat16* nBh = smb + nb * BUF_ELEMS + 2 * A_ELEMS;
            __nv_bfloat16* nBl = nBh + B_ELEMS;
#pragma unroll
            for (int j = 0; j < 4; j++) {
                unsigned h01, h23, l01, l23;
                f4_to_hilo(pa[j], h01, h23, l01, l23);
                *reinterpret_cast<uint2*>(&nAh[arow[j] * ASTR + acol[j]]) = make_uint2(h01, h23);
                *reinterpret_cast<uint2*>(&nAl[arow[j] * ASTR + acol[j]]) = make_uint2(l01, l23);
                f4_to_hilo(pb[j], h01, h23, l01, l23);
                *reinterpret_cast<uint2*>(&nBh[brow[j] * BSTR + bcol[j]]) = make_uint2(h01, h23);
                *reinterpret_cast<uint2*>(&nBl[brow[j] * BSTR + bcol[j]]) = make_uint2(l01, l23);
            }
            __syncthreads();
        }
    }

#pragma unroll
    for (int mt = 0; mt < 2; mt++) {
        const int r0 = m0 + wm + mt * 16 + (lane >> 2);
#pragma unroll
        for (int nt = 0; nt < 8; nt++) {
            const int c = n0 + wn + nt * 8 + ((lane & 3) << 1);
            const float b0v = bias[c], b1v = bias[c + 1];
            const float v00 = acc[mt][nt][0] + b0v;
            const float v01 = acc[mt][nt][1] + b1v;
            const float v10 = acc[mt][nt][2] + b0v;
            const float v11 = acc[mt][nt][3] + b1v;
            if (MODE == 0) {
                *(float2*)&C[(size_t)r0 * N + c]       = make_float2(v00, v01);
                *(float2*)&C[(size_t)(r0 + 8) * N + c] = make_float2(v10, v11);
            } else {
                const int b = r0 >> 11;
                const int s = r0 & 2047;
                const int h = c >> 6, d = c & 63;
                const int bh = b * NHEADS + h;
                unsigned hi0, lo0, hi1, lo1;
                hilo2(v00 * scl, v01 * scl, hi0, lo0);
                hilo2(v10 * scl, v11 * scl, hi1, lo1);
                const size_t i0 = ((size_t)bh * S_LEN + s) * DK + d;
                const size_t i1 = ((size_t)bh * S_LEN + s + 8) * DK + d;
                *reinterpret_cast<unsigned*>(&Ch[i0]) = hi0;
                *reinterpret_cast<unsigned*>(&Cl[i0]) = lo0;
                *reinterpret_cast<unsigned*>(&Ch[i1]) = hi1;
                *reinterpret_cast<unsigned*>(&Cl[i1]) = lo1;
            }
        }
    }
}

// ============================================================================
// Phase kernel v3: 16 tokens/block (grid 256), warp handles 2 tokens.
// ============================================================================
#define WPT_STRIDE 1032
#define PHASE_SMEM_BYTES (16 * WPT_STRIDE * 4)

__global__ void __launch_bounds__(256) phase_kernel3(
    const float* __restrict__ x, const float* __restrict__ Wp,
    const float* __restrict__ bp, float* __restrict__ cs, float* __restrict__ sn)
{
    extern __shared__ float WpT[];
    const int tid = threadIdx.x;
    for (int idx = tid; idx < DMODEL * NHEADS; idx += 256) {
        const int k = idx >> 4, h = idx & 15;
        WpT[h * WPT_STRIDE + k] = Wp[idx];
    }
    __syncthreads();

    const int lane = tid & 31;
    const int warp = tid >> 5;
    const int t0 = blockIdx.x * 16 + warp * 2;

    float a0[NHEADS], a1[NHEADS];
#pragma unroll
    for (int h = 0; h < NHEADS; h++) { a0[h] = 0.f; a1[h] = 0.f; }

#pragma unroll 4
    for (int i = 0; i < 32; ++i) {
        const int k = i * 32 + lane;
        const float x0 = x[(size_t)t0 * DMODEL + k];
        const float x1 = x[(size_t)(t0 + 1) * DMODEL + k];
#pragma unroll
        for (int h = 0; h < NHEADS; h++) {
            const float w = WpT[h * WPT_STRIDE + k];
            a0[h] = fmaf(x0, w, a0[h]);
            a1[h] = fmaf(x1, w, a1[h]);
        }
    }

    float p0 = 0.f, p1 = 0.f;
#pragma unroll
    for (int h = 0; h < NHEADS; h++) {
        float v0 = a0[h], v1 = a1[h];
#pragma unroll
        for (int off = 16; off >= 1; off >>= 1) {
            v0 += __shfl_xor_sync(0xffffffffu, v0, off);
            v1 += __shfl_xor_sync(0xffffffffu, v1, off);
        }
        if (lane == h) { p0 = v0; p1 = v1; }
    }

    if (lane < NHEADS) {
        const float bpl = bp[lane];
#pragma unroll
        for (int u = 0; u < 2; u++) {
            const int t = t0 + u;
            const int b = t >> 11, s = t & 2047;
            const int bh = b * NHEADS + lane;
            float sv, cv;
            sincosf((u ? p1 : p0) + bpl, &sv, &cv);
            cs[bh * S_LEN + s] = cv;
            sn[bh * S_LEN + s] = sv;
        }
    }
}

// ============================================================================
// Flash attention via mma.m16n8k16 bf16 hi/lo. TQ=128, TK=128, 8 warps.
// Warp owns 16 query rows x full 128-key width; P stays in registers.
// ============================================================================
#define TSTR   72                       // tile row stride (bf16); 144B == 4 banks mod 32
#define TILE_E (128 * TSTR)             // 9216 elems
#define QH_OFF 0
#define QL_OFF TILE_E
#define BUF0   (2 * TILE_E)             // 18432
#define BUF_BLK (4 * TILE_E)            // KH, KL, VH, VL
#define SMEM_BF16_TOT (2 * TILE_E + 2 * BUF_BLK)          // 92160 elems
#define KC_BYTE_OFF (SMEM_BF16_TOT * 2)                   // 184320
#define ATT_SMEM_BYTES (KC_BYTE_OFF + 4 * 128 * 4)        // 186368

__global__ void __launch_bounds__(256, 1) attn_mma(
    const __nv_bfloat16* __restrict__ Qh, const __nv_bfloat16* __restrict__ Ql,
    const __nv_bfloat16* __restrict__ Kh, const __nv_bfloat16* __restrict__ Kl,
    const __nv_bfloat16* __restrict__ Vh, const __nv_bfloat16* __restrict__ Vl,
    const float* __restrict__ cs, const float* __restrict__ sn,
    const float* __restrict__ alpha, float* __restrict__ O)
{
    extern __shared__ __nv_bfloat16 smb[];
    const unsigned sbase = sptr(smb);
    const int tid  = threadIdx.x;
    const int lane = tid & 31;
    const int warp = tid >> 5;
    const int bh = blockIdx.y;
    const int q0 = blockIdx.x * 128;

    // ---- issue Q tiles + K/V tile 0 (group 0), tile 1 (group 1) ----
    {
        const __nv_bfloat16* qsrc[2] = {Qh, Ql};
#pragma unroll
        for (int t = 0; t < 2; t++)
#pragma unroll
            for (int j = 0; j < 4; j++) {
                const int idx = tid + j * 256;
                const int row = idx >> 3, ch = idx & 7;
                cpa16(sbase + (t * TILE_E + row * TSTR + ch * 8) * 2,
                      qsrc[t] + ((size_t)(bh * S_LEN + q0 + row) * DK + ch * 8));
            }
    }
    const __nv_bfloat16* kvsrc[4] = {Kh, Kl, Vh, Vl};
#pragma unroll 1
    for (int pre = 0; pre < 2; pre++) {
        const int c0 = pre * 128;
#pragma unroll
        for (int t = 0; t < 4; t++) {
            const unsigned dbase = sbase + (BUF0 + pre * BUF_BLK + t * TILE_E) * 2;
#pragma unroll
            for (int j = 0; j < 4; j++) {
                const int idx = tid + j * 256;
                const int row = idx >> 3, ch = idx & 7;
                cpa16(dbase + (row * TSTR + ch * 8) * 2,
                      kvsrc[t] + ((size_t)(bh * S_LEN + c0 + row) * DK + ch * 8));
            }
        }
        if (tid < 64) {
            const int arr = tid >> 5, q = tid & 31;
            const float* s = arr ? sn : cs;
            cpa16(sbase + KC_BYTE_OFF + pre * 1024 + arr * 512 + q * 16,
                  s + (size_t)bh * S_LEN + c0 + q * 4);
        }
        cp_commit();
    }

    // per-row phase values (alpha folded)
    const float alp = alpha[bh & (NHEADS - 1)];
    const int rq_lo = q0 + warp * 16 + (lane >> 2);
    const float aqc_lo = alp * cs[bh * S_LEN + rq_lo];
    const float aqs_lo = alp * sn[bh * S_LEN + rq_lo];
    const float aqc_hi = alp * cs[bh * S_LEN + rq_lo + 8];
    const float aqs_hi = alp * sn[bh * S_LEN + rq_lo + 8];

    cp_wait<1>();            // group 0 (Q + tile0) complete
    __syncthreads();

    // ---- Q fragments (held for whole kernel) ----
    const int koff = (lane >> 4) << 3;
    unsigned afh[4][4], afl[4][4];
#pragma unroll
    for (int ks = 0; ks < 4; ks++) {
        const unsigned sa = sbase +
            (QH_OFF + (warp * 16 + (lane & 15)) * TSTR + ks * 16 + koff) * 2;
        ldsm_x4(afh[ks], sa);
        ldsm_x4(afl[ks], sa + TILE_E * 2);
    }

    float m_lo = -1e30f, m_hi = -1e30f, l_lo = 0.f, l_hi = 0.f;
    float o[8][4];
#pragma unroll
    for (int nt = 0; nt < 8; nt++)
#pragma unroll
        for (int e = 0; e < 4; e++) o[nt][e] = 0.f;

    const float* fkc = (const float*)((const char*)smb + KC_BYTE_OFF);

    for (int kt = 0; kt < S_LEN / 128; ++kt) {
        if (kt) { cp_wait<1>(); __syncthreads(); }
        const int buf = kt & 1;
        const unsigned kb = sbase + (BUF0 + buf * BUF_BLK) * 2;

        // ---- QK^T: S[16 x 128] per warp ----
        float acc[16][4];
#pragma unroll
        for (int t = 0; t < 16; t++)
#pragma unroll
            for (int e = 0; e < 4; e++) acc[t][e] = 0.f;

#pragma unroll
        for (int ks = 0; ks < 4; ks++) {
#pragma unroll
            for (int p = 0; p < 8; p++) {
                unsigned rh[4], rl[4];
                const unsigned ka = kb +
                    ((p * 16 + (lane & 15)) * TSTR + ks * 16 + koff) * 2;
                ldsm_x4(rh, ka);
                ldsm_x4(rl, ka + TILE_E * 2);
                unsigned bh0[2] = {rh[0], rh[2]}, bh1[2] = {rh[1], rh[3]};
                unsigned bl0[2] = {rl[0], rl[2]}, bl1[2] = {rl[1], rl[3]};
                mma_bf16(acc[2 * p],     afh[ks], bh0);
                mma_bf16(acc[2 * p],     afh[ks], bl0);
                mma_bf16(acc[2 * p],     afl[ks], bh0);
                mma_bf16(acc[2 * p + 1], afh[ks], bh1);
                mma_bf16(acc[2 * p + 1], afh[ks], bl1);
                mma_bf16(acc[2 * p + 1], afl[ks], bh1);
            }
        }

        // ---- coherence + online softmax ----
        const float* kcb = fkc + buf * 256;
        float mx_lo = -1e30f, mx_hi = -1e30f;
#pragma unroll
        for (int t = 0; t < 16; t++) {
            const float2 kc2 = *(const float2*)&kcb[t * 8 + ((lane & 3) << 1)];
            const float2 ks2 = *(const float2*)&kcb[128 + t * 8 + ((lane & 3) << 1)];
            acc[t][0] += aqc_lo * kc2.x + aqs_lo * ks2.x;
            acc[t][1] += aqc_lo * kc2.y + aqs_lo * ks2.y;
            acc[t][2] += aqc_hi * kc2.x + aqs_hi * ks2.x;
            acc[t][3] += aqc_hi * kc2.y + aqs_hi * ks2.y;
            mx_lo = fmaxf(mx_lo, fmaxf(acc[t][0], acc[t][1]));
            mx_hi = fmaxf(mx_hi, fmaxf(acc[t][2], acc[t][3]));
        }
        mx_lo = fmaxf(mx_lo, __shfl_xor_sync(0xffffffffu, mx_lo, 1));
        mx_lo = fmaxf(mx_lo, __shfl_xor_sync(0xffffffffu, mx_lo, 2));
        mx_hi = fmaxf(mx_hi, __shfl_xor_sync(0xffffffffu, mx_hi, 1));
        mx_hi = fmaxf(mx_hi, __shfl_xor_sync(0xffffffffu, mx_hi, 2));

        const float mn_lo = fmaxf(m_lo, mx_lo);
        const float mn_hi = fmaxf(m_hi, mx_hi);
        const float cr_lo = __expf(m_lo - mn_lo);
        const float cr_hi = __expf(m_hi - mn_hi);
        m_lo = mn_lo; m_hi = mn_hi;

        float sum_lo = 0.f, sum_hi = 0.f;
#pragma unroll
        for (int t = 0; t < 16; t++) {
            acc[t][0] = __expf(acc[t][0] - m_lo); sum_lo += acc[t][0];
            acc[t][1] = __expf(acc[t][1] - m_lo); sum_lo += acc[t][1];
            acc[t][2] = __expf(acc[t][2] - m_hi); sum_hi += acc[t][2];
            acc[t][3] = __expf(acc[t][3] - m_hi); sum_hi += acc[t][3];
        }
        sum_lo += __shfl_xor_sync(0xffffffffu, sum_lo, 1);
        sum_lo += __shfl_xor_sync(0xffffffffu, sum_lo, 2);
        sum_hi += __shfl_xor_sync(0xffffffffu, sum_hi, 1);
        sum_hi += __shfl_xor_sync(0xffffffffu, sum_hi, 2);
        l_lo = l_lo * cr_lo + sum_lo;
        l_hi = l_hi * cr_hi + sum_hi;

#pragma unroll
        for (int nt = 0; nt < 8; nt++) {
            o[nt][0] *= cr_lo; o[nt][1] *= cr_lo;
            o[nt][2] *= cr_hi; o[nt][3] *= cr_hi;
        }

        // ---- PV: P (registers, hi/lo) x V (smem) ----
        const unsigned vb = kb + 2 * TILE_E * 2;
#pragma unroll
        for (int t2 = 0; t2 < 8; t2++) {
            unsigned aPh[4], aPl[4];
            hilo2(acc[2 * t2][0],     acc[2 * t2][1],     aPh[0], aPl[0]);
            hilo2(acc[2 * t2][2],     acc[2 * t2][3],     aPh[1], aPl[1]);
            hilo2(acc[2 * t2 + 1][0], acc[2 * t2 + 1][1], aPh[2], aPl[2]);
            hilo2(acc[2 * t2 + 1][2], acc[2 * t2 + 1][3], aPh[3], aPl[3]);
#pragma unroll
            for (int dp = 0; dp < 4; dp++) {
                unsigned rh[4], rl[4];
                const unsigned va = vb +
                    ((t2 * 16 + (lane & 15)) * TSTR + dp * 16 + koff) * 2;
                ldsm_x4t(rh, va);
                ldsm_x4t(rl, va + TILE_E * 2);
                unsigned bh0[2] = {rh[0], rh[1]}, bh1[2] = {rh[2], rh[3]};
                unsigned bl0[2] = {rl[0], rl[1]}, bl1[2] = {rl[2], rl[3]};
                mma_bf16(o[2 * dp],     aPh, bh0);
                mma_bf16(o[2 * dp],     aPh, bl0);
                mma_bf16(o[2 * dp],     aPl, bh0);
                mma_bf16(o[2 * dp + 1], aPh, bh1);
                mma_bf16(o[2 * dp + 1], aPh, bl1);
                mma_bf16(o[2 * dp + 1], aPl, bh1);
            }
        }

        __syncthreads();     // all warps done reading buf before refill
        if (kt + 2 < S_LEN / 128) {
            const int c0 = (kt + 2) * 128;
#pragma unroll
            for (int t = 0; t < 4; t++) {
                const unsigned dbase = sbase + (BUF0 + buf * BUF_BLK + t * TILE_E) * 2;
#pragma unroll
                for (int j = 0; j < 4; j++) {
                    const int idx = tid + j * 256;
                    const int row = idx >> 3, ch = idx & 7;
                    cpa16(dbase + (row * TSTR + ch * 8) * 2,
                          kvsrc[t] + ((size_t)(bh * S_LEN + c0 + row) * DK + ch * 8));
                }
            }
            if (tid < 64) {
                const int arr = tid >> 5, q = tid & 31;
                const float* s = arr ? sn : cs;
                cpa16(sbase + KC_BYTE_OFF + buf * 1024 + arr * 512 + q * 16,
                      s + (size_t)bh * S_LEN + c0 + q * 4);
            }
        }
        cp_commit();
    }

    // ---- epilogue ----
    const int b = bh >> 4, h = bh & 15;
    const float inv_lo = 1.f / l_lo;
    const float inv_hi = 1.f / l_hi;
    const int row_lo = q0 + warp * 16 + (lane >> 2);
#pragma unroll
    for (int nt = 0; nt < 8; nt++) {
        const int col = h * DK + nt * 8 + ((lane & 3) << 1);
        *(float2*)&O[((size_t)b * S_LEN + row_lo) * DMODEL + col] =
            make_float2(o[nt][0] * inv_lo, o[nt][1] * inv_lo);
        *(float2*)&O[((size_t)b * S_LEN + row_lo + 8) * DMODEL + col] =
            make_float2(o[nt][2] * inv_hi, o[nt][3] * inv_hi);
    }
}

// ============================================================================
extern "C" void kernel_launch(void* const* d_in, const int* in_sizes, int n_in,
                              void* d_out, int out_size)
{
    const float* x     = (const float*)d_in[0];
    const float* Wq    = (const float*)d_in[1];
    const float* bq    = (const float*)d_in[2];
    const float* Wk    = (const float*)d_in[3];
    const float* bk    = (const float*)d_in[4];
    const float* Wv    = (const float*)d_in[5];
    const float* bv    = (const float*)d_in[6];
    const float* Wo    = (const float*)d_in[7];
    const float* bo    = (const float*)d_in[8];
    const float* Wp    = (const float*)d_in[9];
    const float* bp    = (const float*)d_in[10];
    const float* alpha = (const float*)d_in[11];
    float* out = (float*)d_out;

    __nv_bfloat16 *pQh, *pQl, *pKh, *pKl, *pVh, *pVl;
    float *pO, *pc, *ps;
    cudaGetSymbolAddress((void**)&pQh, g_Qh);
    cudaGetSymbolAddress((void**)&pQl, g_Ql);
    cudaGetSymbolAddress((void**)&pKh, g_Kh);
    cudaGetSymbolAddress((void**)&pKl, g_Kl);
    cudaGetSymbolAddress((void**)&pVh, g_Vh);
    cudaGetSymbolAddress((void**)&pVl, g_Vl);
    cudaGetSymbolAddress((void**)&pO, g_O);
    cudaGetSymbolAddress((void**)&pc, g_cs);
    cudaGetSymbolAddress((void**)&ps, g_sn);

    cudaFuncSetAttribute(gemm_mma<0>, cudaFuncAttributeMaxDynamicSharedMemorySize, MMA_SMEM_BYTES);
    cudaFuncSetAttribute(gemm_mma<1>, cudaFuncAttributeMaxDynamicSharedMemorySize, MMA_SMEM_BYTES);
    cudaFuncSetAttribute(phase_kernel3, cudaFuncAttributeMaxDynamicSharedMemorySize, PHASE_SMEM_BYTES);
    cudaFuncSetAttribute(attn_mma, cudaFuncAttributeMaxDynamicSharedMemorySize, ATT_SMEM_BYTES);

    dim3 g(DMODEL / 128, NTOK / 128);   // (8, 32)

    gemm_mma<1><<<g, 256, MMA_SMEM_BYTES>>>(x, Wq, bq, nullptr, pQh, pQl, 0.125f,
                                            NTOK, DMODEL, DMODEL);
    gemm_mma<1><<<g, 256, MMA_SMEM_BYTES>>>(x, Wk, bk, nullptr, pKh, pKl, 1.0f,
                                            NTOK, DMODEL, DMODEL);
    gemm_mma<1><<<g, 256, MMA_SMEM_BYTES>>>(x, Wv, bv, nullptr, pVh, pVl, 1.0f,
                                            NTOK, DMODEL, DMODEL);
    phase_kernel3<<<NTOK / 16, 256, PHASE_SMEM_BYTES>>>(x, Wp, bp, pc, ps);

    attn_mma<<<dim3(S_LEN / 128, BHALL), 256, ATT_SMEM_BYTES>>>(
        pQh, pQl, pKh, pKl, pVh, pVl, pc, ps, alpha, pO);

    gemm_mma<0><<<g, 256, MMA_SMEM_BYTES>>>(pO, Wo, bo, out, nullptr, nullptr, 1.0f,
                                            NTOK, DMODEL, DMODEL);
}

// round 8
// speedup vs baseline: 2.6836x; 1.0017x over previous
#include <cuda_runtime.h>
#include <cuda_bf16.h>
#include <math.h>

#define S_LEN   2048
#define DMODEL  1024
#define NHEADS  16
#define DK      64
#define BATCH   2
#define NTOK    (BATCH * S_LEN)     // 4096
#define BHALL   (BATCH * NHEADS)    // 32

// ---------------- scratch (device globals; no allocation allowed) ----------
__device__ __nv_bfloat16 g_Qh[BHALL * S_LEN * DK];
__device__ __nv_bfloat16 g_Ql[BHALL * S_LEN * DK];
__device__ __nv_bfloat16 g_Kh[BHALL * S_LEN * DK];
__device__ __nv_bfloat16 g_Kl[BHALL * S_LEN * DK];
__device__ __nv_bfloat16 g_Vh[BHALL * S_LEN * DK];
__device__ __nv_bfloat16 g_Vl[BHALL * S_LEN * DK];
__device__ float g_O[NTOK * DMODEL];
__device__ float g_cs[BHALL * S_LEN];
__device__ float g_sn[BHALL * S_LEN];

// ============================================================================
// MMA / ldmatrix / cp.async helpers
// ============================================================================
__device__ __forceinline__ unsigned sptr(const void* p) {
    return (unsigned)__cvta_generic_to_shared(p);
}
__device__ __forceinline__ void ldsm_x4(unsigned r[4], unsigned sa) {
    asm volatile("ldmatrix.sync.aligned.m8n8.x4.shared.b16 {%0,%1,%2,%3}, [%4];"
                 : "=r"(r[0]), "=r"(r[1]), "=r"(r[2]), "=r"(r[3]) : "r"(sa));
}
__device__ __forceinline__ void ldsm_x4t(unsigned r[4], unsigned sa) {
    asm volatile("ldmatrix.sync.aligned.m8n8.x4.trans.shared.b16 {%0,%1,%2,%3}, [%4];"
                 : "=r"(r[0]), "=r"(r[1]), "=r"(r[2]), "=r"(r[3]) : "r"(sa));
}
__device__ __forceinline__ void mma_bf16(float c[4], const unsigned a[4], const unsigned b[2]) {
    asm volatile(
        "mma.sync.aligned.m16n8k16.row.col.f32.bf16.bf16.f32 "
        "{%0,%1,%2,%3}, {%4,%5,%6,%7}, {%8,%9}, {%0,%1,%2,%3};"
        : "+f"(c[0]), "+f"(c[1]), "+f"(c[2]), "+f"(c[3])
        : "r"(a[0]), "r"(a[1]), "r"(a[2]), "r"(a[3]), "r"(b[0]), "r"(b[1]));
}
__device__ __forceinline__ void cpa16(unsigned d, const void* s) {
    asm volatile("cp.async.cg.shared.global [%0], [%1], 16;" :: "r"(d), "l"(s));
}
__device__ __forceinline__ void cp_commit() {
    asm volatile("cp.async.commit_group;");
}
template <int N> __device__ __forceinline__ void cp_wait() {
    asm volatile("cp.async.wait_group %0;" :: "n"(N));
}
// pack 2 floats -> bf16x2 u32, element0 = e0 (low half)
__device__ __forceinline__ unsigned packbf(float e0, float e1) {
    unsigned r;
    asm("cvt.rn.bf16x2.f32 %0, %1, %2;" : "=r"(r) : "f"(e1), "f"(e0));
    return r;
}
__device__ __forceinline__ void hilo2(float e0, float e1, unsigned& hi, unsigned& lo) {
    hi = packbf(e0, e1);
    const float f0 = __uint_as_float(hi << 16);
    const float f1 = __uint_as_float(hi & 0xffff0000u);
    lo = packbf(e0 - f0, e1 - f1);
}

// float4 -> (hi bf16 x4 as 2x u32) + (lo bf16 x4 as 2x u32)
__device__ __forceinline__ void f4_to_hilo(const float4 v,
    unsigned& h01, unsigned& h23, unsigned& l01, unsigned& l23)
{
    hilo2(v.x, v.y, h01, l01);
    hilo2(v.z, v.w, h23, l23);
}

// ============================================================================
// Tensor-core GEMM: 128x128 tiles, K-chunk 32, 256 thr, bf16 hi/lo 3-term.
// MODE 0: fp32 C[m*N + n]                           (token-major, final proj)
// MODE 1: bf16 hi/lo head-major Ch/Cl[(bh*S+s)*64+d], v=(acc+bias)*scl (QKV)
// ============================================================================
#define ASTR 40
#define BSTR 136
#define A_ELEMS (128 * ASTR)
#define B_ELEMS (32 * BSTR)
#define BUF_ELEMS (2 * A_ELEMS + 2 * B_ELEMS)
#define MMA_SMEM_BYTES (2 * BUF_ELEMS * 2)

template <int MODE>
__global__ void __launch_bounds__(256) gemm_mma(
    const float* __restrict__ A, const float* __restrict__ B,
    const float* __restrict__ bias, float* __restrict__ C,
    __nv_bfloat16* __restrict__ Ch, __nv_bfloat16* __restrict__ Cl,
    float scl, int M, int N, int K)
{
    extern __shared__ __nv_bfloat16 smb[];
    const int tid  = threadIdx.x;
    const int lane = tid & 31;
    const int warp = tid >> 5;
    const int wm = (warp >> 1) * 32;
    const int wn = (warp & 1) * 64;
    const int m0 = blockIdx.y * 128;
    const int n0 = blockIdx.x * 128;

    int arow[4], acol[4], brow[4], bcol[4];
#pragma unroll
    for (int j = 0; j < 4; j++) {
        const int idx = tid + j * 256;
        arow[j] = idx >> 3;  acol[j] = (idx & 7) << 2;
        brow[j] = idx >> 5;  bcol[j] = (idx & 31) << 2;
    }

    float4 pa[4], pb[4];
#pragma unroll
    for (int j = 0; j < 4; j++) {
        pa[j] = *(const float4*)&A[(size_t)(m0 + arow[j]) * K + acol[j]];
        pb[j] = *(const float4*)&B[(size_t)brow[j] * N + n0 + bcol[j]];
    }
    {
        __nv_bfloat16* Ah = smb;
        __nv_bfloat16* Al = Ah + A_ELEMS;
        __nv_bfloat16* Bh = smb + 2 * A_ELEMS;
        __nv_bfloat16* Bl = Bh + B_ELEMS;
#pragma unroll
        for (int j = 0; j < 4; j++) {
            unsigned h01, h23, l01, l23;
            f4_to_hilo(pa[j], h01, h23, l01, l23);
            *reinterpret_cast<uint2*>(&Ah[arow[j] * ASTR + acol[j]]) = make_uint2(h01, h23);
            *reinterpret_cast<uint2*>(&Al[arow[j] * ASTR + acol[j]]) = make_uint2(l01, l23);
            f4_to_hilo(pb[j], h01, h23, l01, l23);
            *reinterpret_cast<uint2*>(&Bh[brow[j] * BSTR + bcol[j]]) = make_uint2(h01, h23);
            *reinterpret_cast<uint2*>(&Bl[brow[j] * BSTR + bcol[j]]) = make_uint2(l01, l23);
        }
    }
    __syncthreads();

    float acc[2][8][4];
#pragma unroll
    for (int mt = 0; mt < 2; mt++)
#pragma unroll
        for (int nt = 0; nt < 8; nt++)
#pragma unroll
            for (int e = 0; e < 4; e++) acc[mt][nt][e] = 0.f;

    const int KT = K / 32;
    for (int kt = 0; kt < KT; ++kt) {
        const int buf = kt & 1;
        if (kt + 1 < KT) {
            const int k0 = (kt + 1) * 32;
#pragma unroll
            for (int j = 0; j < 4; j++) {
                pa[j] = *(const float4*)&A[(size_t)(m0 + arow[j]) * K + k0 + acol[j]];
                pb[j] = *(const float4*)&B[(size_t)(k0 + brow[j]) * N + n0 + bcol[j]];
            }
        }

        const __nv_bfloat16* Ah = smb + buf * BUF_ELEMS;
        const __nv_bfloat16* Bh = smb + buf * BUF_ELEMS + 2 * A_ELEMS;

#pragma unroll
        for (int kk = 0; kk < 32; kk += 16) {
            unsigned afh[2][4], afl[2][4];
#pragma unroll
            for (int mt = 0; mt < 2; mt++) {
                unsigned sa = sptr(&Ah[(wm + mt * 16 + (lane & 15)) * ASTR
                                       + kk + ((lane >> 4) << 3)]);
                ldsm_x4(afh[mt], sa);
                ldsm_x4(afl[mt], sa + A_ELEMS * 2);
            }
            unsigned bfh[8][2], bfl[8][2];
#pragma unroll
            for (int np = 0; np < 4; np++) {
                unsigned sb = sptr(&Bh[(kk + (lane & 15)) * BSTR
                                       + wn + np * 16 + ((lane >> 4) << 3)]);
                unsigned r[4];
                ldsm_x4t(r, sb);
                bfh[2 * np][0] = r[0]; bfh[2 * np][1] = r[1];
                bfh[2 * np + 1][0] = r[2]; bfh[2 * np + 1][1] = r[3];
                ldsm_x4t(r, sb + B_ELEMS * 2);
                bfl[2 * np][0] = r[0]; bfl[2 * np][1] = r[1];
                bfl[2 * np + 1][0] = r[2]; bfl[2 * np + 1][1] = r[3];
            }
#pragma unroll
            for (int mt = 0; mt < 2; mt++)
#pragma unroll
                for (int nt = 0; nt < 8; nt++) {
                    mma_bf16(acc[mt][nt], afh[mt], bfh[nt]);
                    mma_bf16(acc[mt][nt], afh[mt], bfl[nt]);
                    mma_bf16(acc[mt][nt], afl[mt], bfh[nt]);
                }
        }

        if (kt + 1 < KT) {
            const int nb = 1 - buf;
            __nv_bfloat16* nAh = smb + nb * BUF_ELEMS;
            __nv_bfloat16* nAl = nAh + A_ELEMS;
            __nv_bfloat16* nBh = smb + nb * BUF_ELEMS + 2 * A_ELEMS;
            __nv_bfloat16* nBl = nBh + B_ELEMS;
#pragma unroll
            for (int j = 0; j < 4; j++) {
                unsigned h01, h23, l01, l23;
                f4_to_hilo(pa[j], h01, h23, l01, l23);
                *reinterpret_cast<uint2*>(&nAh[arow[j] * ASTR + acol[j]]) = make_uint2(h01, h23);
                *reinterpret_cast<uint2*>(&nAl[arow[j] * ASTR + acol[j]]) = make_uint2(l01, l23);
                f4_to_hilo(pb[j], h01, h23, l01, l23);
                *reinterpret_cast<uint2*>(&nBh[brow[j] * BSTR + bcol[j]]) = make_uint2(h01, h23);
                *reinterpret_cast<uint2*>(&nBl[brow[j] * BSTR + bcol[j]]) = make_uint2(l01, l23);
            }
            __syncthreads();
        }
    }

#pragma unroll
    for (int mt = 0; mt < 2; mt++) {
        const int r0 = m0 + wm + mt * 16 + (lane >> 2);
#pragma unroll
        for (int nt = 0; nt < 8; nt++) {
            const int c = n0 + wn + nt * 8 + ((lane & 3) << 1);
            const float b0v = bias[c], b1v = bias[c + 1];
            const float v00 = acc[mt][nt][0] + b0v;
            const float v01 = acc[mt][nt][1] + b1v;
            const float v10 = acc[mt][nt][2] + b0v;
            const float v11 = acc[mt][nt][3] + b1v;
            if (MODE == 0) {
                *(float2*)&C[(size_t)r0 * N + c]       = make_float2(v00, v01);
                *(float2*)&C[(size_t)(r0 + 8) * N + c] = make_float2(v10, v11);
            } else {
                const int b = r0 >> 11;
                const int s = r0 & 2047;
                const int h = c >> 6, d = c & 63;
                const int bh = b * NHEADS + h;
                unsigned hi0, lo0, hi1, lo1;
                hilo2(v00 * scl, v01 * scl, hi0, lo0);
                hilo2(v10 * scl, v11 * scl, hi1, lo1);
                const size_t i0 = ((size_t)bh * S_LEN + s) * DK + d;
                const size_t i1 = ((size_t)bh * S_LEN + s + 8) * DK + d;
                *reinterpret_cast<unsigned*>(&Ch[i0]) = hi0;
                *reinterpret_cast<unsigned*>(&Cl[i0]) = lo0;
                *reinterpret_cast<unsigned*>(&Ch[i1]) = hi1;
                *reinterpret_cast<unsigned*>(&Cl[i1]) = lo1;
            }
        }
    }
}

// ============================================================================
// Phase kernel v3: 16 tokens/block (grid 256), warp handles 2 tokens.
// ============================================================================
#define WPT_STRIDE 1032
#define PHASE_SMEM_BYTES (16 * WPT_STRIDE * 4)

__global__ void __launch_bounds__(256) phase_kernel3(
    const float* __restrict__ x, const float* __restrict__ Wp,
    const float* __restrict__ bp, float* __restrict__ cs, float* __restrict__ sn)
{
    extern __shared__ float WpT[];
    const int tid = threadIdx.x;
    for (int idx = tid; idx < DMODEL * NHEADS; idx += 256) {
        const int k = idx >> 4, h = idx & 15;
        WpT[h * WPT_STRIDE + k] = Wp[idx];
    }
    __syncthreads();

    const int lane = tid & 31;
    const int warp = tid >> 5;
    const int t0 = blockIdx.x * 16 + warp * 2;

    float a0[NHEADS], a1[NHEADS];
#pragma unroll
    for (int h = 0; h < NHEADS; h++) { a0[h] = 0.f; a1[h] = 0.f; }

#pragma unroll 4
    for (int i = 0; i < 32; ++i) {
        const int k = i * 32 + lane;
        const float x0 = x[(size_t)t0 * DMODEL + k];
        const float x1 = x[(size_t)(t0 + 1) * DMODEL + k];
#pragma unroll
        for (int h = 0; h < NHEADS; h++) {
            const float w = WpT[h * WPT_STRIDE + k];
            a0[h] = fmaf(x0, w, a0[h]);
            a1[h] = fmaf(x1, w, a1[h]);
        }
    }

    float p0 = 0.f, p1 = 0.f;
#pragma unroll
    for (int h = 0; h < NHEADS; h++) {
        float v0 = a0[h], v1 = a1[h];
#pragma unroll
        for (int off = 16; off >= 1; off >>= 1) {
            v0 += __shfl_xor_sync(0xffffffffu, v0, off);
            v1 += __shfl_xor_sync(0xffffffffu, v1, off);
        }
        if (lane == h) { p0 = v0; p1 = v1; }
    }

    if (lane < NHEADS) {
        const float bpl = bp[lane];
#pragma unroll
        for (int u = 0; u < 2; u++) {
            const int t = t0 + u;
            const int b = t >> 11, s = t & 2047;
            const int bh = b * NHEADS + lane;
            float sv, cv;
            sincosf((u ? p1 : p0) + bpl, &sv, &cv);
            cs[bh * S_LEN + s] = cv;
            sn[bh * S_LEN + s] = sv;
        }
    }
}

// ============================================================================
// Flash attention via mma.m16n8k16 bf16 hi/lo. TQ=128, TK=128, 8 warps.
// Warp owns 16 query rows x full 128-key width; P stays in registers.
// ============================================================================
#define TSTR   72                       // tile row stride (bf16); 144B == 4 banks mod 32
#define TILE_E (128 * TSTR)             // 9216 elems
#define QH_OFF 0
#define QL_OFF TILE_E
#define BUF0   (2 * TILE_E)             // 18432
#define BUF_BLK (4 * TILE_E)            // KH, KL, VH, VL
#define SMEM_BF16_TOT (2 * TILE_E + 2 * BUF_BLK)          // 92160 elems
#define KC_BYTE_OFF (SMEM_BF16_TOT * 2)                   // 184320
#define ATT_SMEM_BYTES (KC_BYTE_OFF + 4 * 128 * 4)        // 186368

__global__ void __launch_bounds__(256, 1) attn_mma(
    const __nv_bfloat16* __restrict__ Qh, const __nv_bfloat16* __restrict__ Ql,
    const __nv_bfloat16* __restrict__ Kh, const __nv_bfloat16* __restrict__ Kl,
    const __nv_bfloat16* __restrict__ Vh, const __nv_bfloat16* __restrict__ Vl,
    const float* __restrict__ cs, const float* __restrict__ sn,
    const float* __restrict__ alpha, float* __restrict__ O)
{
    extern __shared__ __nv_bfloat16 smb[];
    const unsigned sbase = sptr(smb);
    const int tid  = threadIdx.x;
    const int lane = tid & 31;
    const int warp = tid >> 5;
    const int bh = blockIdx.y;
    const int q0 = blockIdx.x * 128;

    // ---- issue Q tiles + K/V tile 0 (group 0), tile 1 (group 1) ----
    {
        const __nv_bfloat16* qsrc[2] = {Qh, Ql};
#pragma unroll
        for (int t = 0; t < 2; t++)
#pragma unroll
            for (int j = 0; j < 4; j++) {
                const int idx = tid + j * 256;
                const int row = idx >> 3, ch = idx & 7;
                cpa16(sbase + (t * TILE_E + row * TSTR + ch * 8) * 2,
                      qsrc[t] + ((size_t)(bh * S_LEN + q0 + row) * DK + ch * 8));
            }
    }
    const __nv_bfloat16* kvsrc[4] = {Kh, Kl, Vh, Vl};
#pragma unroll 1
    for (int pre = 0; pre < 2; pre++) {
        const int c0 = pre * 128;
#pragma unroll
        for (int t = 0; t < 4; t++) {
            const unsigned dbase = sbase + (BUF0 + pre * BUF_BLK + t * TILE_E) * 2;
#pragma unroll
            for (int j = 0; j < 4; j++) {
                const int idx = tid + j * 256;
                const int row = idx >> 3, ch = idx & 7;
                cpa16(dbase + (row * TSTR + ch * 8) * 2,
                      kvsrc[t] + ((size_t)(bh * S_LEN + c0 + row) * DK + ch * 8));
            }
        }
        if (tid < 64) {
            const int arr = tid >> 5, q = tid & 31;
            const float* s = arr ? sn : cs;
            cpa16(sbase + KC_BYTE_OFF + pre * 1024 + arr * 512 + q * 16,
                  s + (size_t)bh * S_LEN + c0 + q * 4);
        }
        cp_commit();
    }

    // per-row phase values (alpha folded)
    const float alp = alpha[bh & (NHEADS - 1)];
    const int rq_lo = q0 + warp * 16 + (lane >> 2);
    const float aqc_lo = alp * cs[bh * S_LEN + rq_lo];
    const float aqs_lo = alp * sn[bh * S_LEN + rq_lo];
    const float aqc_hi = alp * cs[bh * S_LEN + rq_lo + 8];
    const float aqs_hi = alp * sn[bh * S_LEN + rq_lo + 8];

    cp_wait<1>();            // group 0 (Q + tile0) complete
    __syncthreads();

    // ---- Q fragments (held for whole kernel) ----
    const int koff = (lane >> 4) << 3;
    unsigned afh[4][4], afl[4][4];
#pragma unroll
    for (int ks = 0; ks < 4; ks++) {
        const unsigned sa = sbase +
            (QH_OFF + (warp * 16 + (lane & 15)) * TSTR + ks * 16 + koff) * 2;
        ldsm_x4(afh[ks], sa);
        ldsm_x4(afl[ks], sa + TILE_E * 2);
    }

    float m_lo = -1e30f, m_hi = -1e30f, l_lo = 0.f, l_hi = 0.f;
    float o[8][4];
#pragma unroll
    for (int nt = 0; nt < 8; nt++)
#pragma unroll
        for (int e = 0; e < 4; e++) o[nt][e] = 0.f;

    const float* fkc = (const float*)((const char*)smb + KC_BYTE_OFF);

    for (int kt = 0; kt < S_LEN / 128; ++kt) {
        if (kt) { cp_wait<1>(); __syncthreads(); }
        const int buf = kt & 1;
        const unsigned kb = sbase + (BUF0 + buf * BUF_BLK) * 2;

        // ---- QK^T: S[16 x 128] per warp ----
        float acc[16][4];
#pragma unroll
        for (int t = 0; t < 16; t++)
#pragma unroll
            for (int e = 0; e < 4; e++) acc[t][e] = 0.f;

#pragma unroll
        for (int ks = 0; ks < 4; ks++) {
#pragma unroll
            for (int p = 0; p < 8; p++) {
                unsigned rh[4], rl[4];
                const unsigned ka = kb +
                    ((p * 16 + (lane & 15)) * TSTR + ks * 16 + koff) * 2;
                ldsm_x4(rh, ka);
                ldsm_x4(rl, ka + TILE_E * 2);
                unsigned bh0[2] = {rh[0], rh[2]}, bh1[2] = {rh[1], rh[3]};
                unsigned bl0[2] = {rl[0], rl[2]}, bl1[2] = {rl[1], rl[3]};
                mma_bf16(acc[2 * p],     afh[ks], bh0);
                mma_bf16(acc[2 * p],     afh[ks], bl0);
                mma_bf16(acc[2 * p],     afl[ks], bh0);
                mma_bf16(acc[2 * p + 1], afh[ks], bh1);
                mma_bf16(acc[2 * p + 1], afh[ks], bl1);
                mma_bf16(acc[2 * p + 1], afl[ks], bh1);
            }
        }

        // ---- coherence + online softmax ----
        const float* kcb = fkc + buf * 256;
        float mx_lo = -1e30f, mx_hi = -1e30f;
#pragma unroll
        for (int t = 0; t < 16; t++) {
            const float2 kc2 = *(const float2*)&kcb[t * 8 + ((lane & 3) << 1)];
            const float2 ks2 = *(const float2*)&kcb[128 + t * 8 + ((lane & 3) << 1)];
            acc[t][0] += aqc_lo * kc2.x + aqs_lo * ks2.x;
            acc[t][1] += aqc_lo * kc2.y + aqs_lo * ks2.y;
            acc[t][2] += aqc_hi * kc2.x + aqs_hi * ks2.x;
            acc[t][3] += aqc_hi * kc2.y + aqs_hi * ks2.y;
            mx_lo = fmaxf(mx_lo, fmaxf(acc[t][0], acc[t][1]));
            mx_hi = fmaxf(mx_hi, fmaxf(acc[t][2], acc[t][3]));
        }
        mx_lo = fmaxf(mx_lo, __shfl_xor_sync(0xffffffffu, mx_lo, 1));
        mx_lo = fmaxf(mx_lo, __shfl_xor_sync(0xffffffffu, mx_lo, 2));
        mx_hi = fmaxf(mx_hi, __shfl_xor_sync(0xffffffffu, mx_hi, 1));
        mx_hi = fmaxf(mx_hi, __shfl_xor_sync(0xffffffffu, mx_hi, 2));

        const float mn_lo = fmaxf(m_lo, mx_lo);
        const float mn_hi = fmaxf(m_hi, mx_hi);
        const float cr_lo = __expf(m_lo - mn_lo);
        const float cr_hi = __expf(m_hi - mn_hi);
        m_lo = mn_lo; m_hi = mn_hi;

        float sum_lo = 0.f, sum_hi = 0.f;
#pragma unroll
        for (int t = 0; t < 16; t++) {
            acc[t][0] = __expf(acc[t][0] - m_lo); sum_lo += acc[t][0];
            acc[t][1] = __expf(acc[t][1] - m_lo); sum_lo += acc[t][1];
            acc[t][2] = __expf(acc[t][2] - m_hi); sum_hi += acc[t][2];
            acc[t][3] = __expf(acc[t][3] - m_hi); sum_hi += acc[t][3];
        }
        sum_lo += __shfl_xor_sync(0xffffffffu, sum_lo, 1);
        sum_lo += __shfl_xor_sync(0xffffffffu, sum_lo, 2);
        sum_hi += __shfl_xor_sync(0xffffffffu, sum_hi, 1);
        sum_hi += __shfl_xor_sync(0xffffffffu, sum_hi, 2);
        l_lo = l_lo * cr_lo + sum_lo;
        l_hi = l_hi * cr_hi + sum_hi;

#pragma unroll
        for (int nt = 0; nt < 8; nt++) {
            o[nt][0] *= cr_lo; o[nt][1] *= cr_lo;
            o[nt][2] *= cr_hi; o[nt][3] *= cr_hi;
        }

        // ---- PV: P (registers, hi/lo) x V (smem) ----
        const unsigned vb = kb + 2 * TILE_E * 2;
#pragma unroll
        for (int t2 = 0; t2 < 8; t2++) {
            unsigned aPh[4], aPl[4];
            hilo2(acc[2 * t2][0],     acc[2 * t2][1],     aPh[0], aPl[0]);
            hilo2(acc[2 * t2][2],     acc[2 * t2][3],     aPh[1], aPl[1]);
            hilo2(acc[2 * t2 + 1][0], acc[2 * t2 + 1][1], aPh[2], aPl[2]);
            hilo2(acc[2 * t2 + 1][2], acc[2 * t2 + 1][3], aPh[3], aPl[3]);
#pragma unroll
            for (int dp = 0; dp < 4; dp++) {
                unsigned rh[4], rl[4];
                const unsigned va = vb +
                    ((t2 * 16 + (lane & 15)) * TSTR + dp * 16 + koff) * 2;
                ldsm_x4t(rh, va);
                ldsm_x4t(rl, va + TILE_E * 2);
                unsigned bh0[2] = {rh[0], rh[1]}, bh1[2] = {rh[2], rh[3]};
                unsigned bl0[2] = {rl[0], rl[1]}, bl1[2] = {rl[2], rl[3]};
                mma_bf16(o[2 * dp],     aPh, bh0);
                mma_bf16(o[2 * dp],     aPh, bl0);
                mma_bf16(o[2 * dp],     aPl, bh0);
                mma_bf16(o[2 * dp + 1], aPh, bh1);
                mma_bf16(o[2 * dp + 1], aPh, bl1);
                mma_bf16(o[2 * dp + 1], aPl, bh1);
            }
        }

        __syncthreads();     // all warps done reading buf before refill
        if (kt + 2 < S_LEN / 128) {
            const int c0 = (kt + 2) * 128;
#pragma unroll
            for (int t = 0; t < 4; t++) {
                const unsigned dbase = sbase + (BUF0 + buf * BUF_BLK + t * TILE_E) * 2;
#pragma unroll
                for (int j = 0; j < 4; j++) {
                    const int idx = tid + j * 256;
                    const int row = idx >> 3, ch = idx & 7;
                    cpa16(dbase + (row * TSTR + ch * 8) * 2,
                          kvsrc[t] + ((size_t)(bh * S_LEN + c0 + row) * DK + ch * 8));
                }
            }
            if (tid < 64) {
                const int arr = tid >> 5, q = tid & 31;
                const float* s = arr ? sn : cs;
                cpa16(sbase + KC_BYTE_OFF + buf * 1024 + arr * 512 + q * 16,
                      s + (size_t)bh * S_LEN + c0 + q * 4);
            }
        }
        cp_commit();
    }

    // ---- epilogue ----
    const int b = bh >> 4, h = bh & 15;
    const float inv_lo = 1.f / l_lo;
    const float inv_hi = 1.f / l_hi;
    const int row_lo = q0 + warp * 16 + (lane >> 2);
#pragma unroll
    for (int nt = 0; nt < 8; nt++) {
        const int col = h * DK + nt * 8 + ((lane & 3) << 1);
        *(float2*)&O[((size_t)b * S_LEN + row_lo) * DMODEL + col] =
            make_float2(o[nt][0] * inv_lo, o[nt][1] * inv_lo);
        *(float2*)&O[((size_t)b * S_LEN + row_lo + 8) * DMODEL + col] =
            make_float2(o[nt][2] * inv_hi, o[nt][3] * inv_hi);
    }
}

// ============================================================================
extern "C" void kernel_launch(void* const* d_in, const int* in_sizes, int n_in,
                              void* d_out, int out_size)
{
    const float* x     = (const float*)d_in[0];
    const float* Wq    = (const float*)d_in[1];
    const float* bq    = (const float*)d_in[2];
    const float* Wk    = (const float*)d_in[3];
    const float* bk    = (const float*)d_in[4];
    const float* Wv    = (const float*)d_in[5];
    const float* bv    = (const float*)d_in[6];
    const float* Wo    = (const float*)d_in[7];
    const float* bo    = (const float*)d_in[8];
    const float* Wp    = (const float*)d_in[9];
    const float* bp    = (const float*)d_in[10];
    const float* alpha = (const float*)d_in[11];
    float* out = (float*)d_out;

    __nv_bfloat16 *pQh, *pQl, *pKh, *pKl, *pVh, *pVl;
    float *pO, *pc, *ps;
    cudaGetSymbolAddress((void**)&pQh, g_Qh);
    cudaGetSymbolAddress((void**)&pQl, g_Ql);
    cudaGetSymbolAddress((void**)&pKh, g_Kh);
    cudaGetSymbolAddress((void**)&pKl, g_Kl);
    cudaGetSymbolAddress((void**)&pVh, g_Vh);
    cudaGetSymbolAddress((void**)&pVl, g_Vl);
    cudaGetSymbolAddress((void**)&pO, g_O);
    cudaGetSymbolAddress((void**)&pc, g_cs);
    cudaGetSymbolAddress((void**)&ps, g_sn);

    cudaFuncSetAttribute(gemm_mma<0>, cudaFuncAttributeMaxDynamicSharedMemorySize, MMA_SMEM_BYTES);
    cudaFuncSetAttribute(gemm_mma<1>, cudaFuncAttributeMaxDynamicSharedMemorySize, MMA_SMEM_BYTES);
    cudaFuncSetAttribute(phase_kernel3, cudaFuncAttributeMaxDynamicSharedMemorySize, PHASE_SMEM_BYTES);
    cudaFuncSetAttribute(attn_mma, cudaFuncAttributeMaxDynamicSharedMemorySize, ATT_SMEM_BYTES);

    dim3 g(DMODEL / 128, NTOK / 128);   // (8, 32)

    gemm_mma<1><<<g, 256, MMA_SMEM_BYTES>>>(x, Wq, bq, nullptr, pQh, pQl, 0.125f,
                                            NTOK, DMODEL, DMODEL);
    gemm_mma<1><<<g, 256, MMA_SMEM_BYTES>>>(x, Wk, bk, nullptr, pKh, pKl, 1.0f,
                                            NTOK, DMODEL, DMODEL);
    gemm_mma<1><<<g, 256, MMA_SMEM_BYTES>>>(x, Wv, bv, nullptr, pVh, pVl, 1.0f,
                                            NTOK, DMODEL, DMODEL);
    phase_kernel3<<<NTOK / 16, 256, PHASE_SMEM_BYTES>>>(x, Wp, bp, pc, ps);

    attn_mma<<<dim3(S_LEN / 128, BHALL), 256, ATT_SMEM_BYTES>>>(
        pQh, pQl, pKh, pKl, pVh, pVl, pc, ps, alpha, pO);

    gemm_mma<0><<<g, 256, MMA_SMEM_BYTES>>>(pO, Wo, bo, out, nullptr, nullptr, 1.0f,
                                            NTOK, DMODEL, DMODEL);
}